// round 4
// baseline (speedup 1.0000x reference)
#include <cuda_runtime.h>
#include <cstdint>
#include <math.h>

#define SS 3
#define BB 4
#define CC 256
#define HW 4096
#define EPSf 1e-5f

// ---------------- scratch ----------------------------------------------------
__device__ float g_pooled[BB*SS*CC];
__device__ float g_wmix[BB*SS];
__device__ float g_q [SS*BB*CC*HW];
__device__ float g_k [SS*BB*CC*HW];
__device__ float g_v [SS*BB*CC*HW];
__device__ float g_qt[SS*BB*CC*HW];
__device__ float g_kt[SS*BB*CC*HW];
__device__ float g_vt[SS*BB*CC*HW];
__device__ float g_o [SS*BB*CC*HW];
__device__ float g_integr[BB*CC*HW];
__device__ float g_y2[BB*CC*HW];

__device__ __forceinline__ float gelu_f(float x){
    return 0.5f * x * (1.0f + erff(x * 0.70710678118654752f));
}
__device__ __forceinline__ uint32_t f2tf(float x){
    uint32_t r;
    asm("cvt.rna.tf32.f32 %0, %1;" : "=r"(r) : "f"(x));
    return r;
}
__device__ __forceinline__ void mma8(float c[4], const uint32_t a[4], const uint32_t b[2]){
    asm volatile(
        "mma.sync.aligned.m16n8k8.row.col.f32.tf32.tf32.f32 "
        "{%0,%1,%2,%3}, {%4,%5,%6,%7}, {%8,%9}, {%0,%1,%2,%3};"
        : "+f"(c[0]), "+f"(c[1]), "+f"(c[2]), "+f"(c[3])
        : "r"(a[0]), "r"(a[1]), "r"(a[2]), "r"(a[3]), "r"(b[0]), "r"(b[1]));
}

// ---------------- GEMM building blocks ---------------------------------------
// CTA tile 128x128, BK=32, 256 threads = 8 warps (2 M x 4 N), warp tile 64x32.
// SMEM holds fragments in mma order:
//   A: tiles [k_tile 0..3][m_tile 0..7] of 128 u32, value idx = lane*4 + r
//      (r0=(m,k), r1=(m+8,k), r2=(m,k+4), r3=(m+8,k+4))   -> LDS.128 per tile
//   B: tiles [k_tile 0..3][n_tile 0..15] of 64 u32, idx = lane*2 + r
//      (r0=(k,n), r1=(k+4,n))                              -> LDS.64 per tile
// Double buffered: As buf = 4096 u32 (16KB), Bs buf = 4096 u32.

__device__ __forceinline__ void fetchA(float4 v[4], const float* Wt, int lda, int tid){
    int m = tid >> 1, kh = (tid & 1) * 16;
    const float4* s = (const float4*)(Wt + (size_t)m*lda + kh);
    v[0]=s[0]; v[1]=s[1]; v[2]=s[2]; v[3]=s[3];
}
__device__ __forceinline__ void storeA(uint32_t* As, const float4 v[4], int tid){
    int m = tid >> 1, kh = (tid & 1) * 16;
    const float* f = (const float*)v;
    int m_tile = m >> 4, ml = m & 15, g = ml & 7, hi_m = ml >> 3;
    #pragma unroll
    for(int i = 0; i < 16; i++){
        int k = kh + i;
        int k_tile = k >> 3, kt = k & 7, tg = kt & 3, hi_k = kt >> 2;
        As[(k_tile*8 + m_tile)*128 + (g*4 + tg)*4 + hi_m + 2*hi_k] = f2tf(f[i]);
    }
}
__device__ __forceinline__ void fetchB(float4 v[4], const float* Xt, int stride, int tid){
    int k = tid >> 3, nb = (tid & 7) * 16;
    const float4* s = (const float4*)(Xt + (size_t)k*stride + nb);
    v[0]=s[0]; v[1]=s[1]; v[2]=s[2]; v[3]=s[3];
}
__device__ __forceinline__ void storeB(uint32_t* Bs, const float* f, int tid, float scl){
    int k = tid >> 3, nb = (tid & 7) * 16;
    int k_tile = k >> 3, kt = k & 7, tg = kt & 3, hi_k = kt >> 2;
    #pragma unroll
    for(int j = 0; j < 16; j++){
        int n = nb + j;
        int n_tile = n >> 3, g = n & 7;
        Bs[(k_tile*16 + n_tile)*64 + (g*4 + tg)*2 + hi_k] = f2tf(f[j]*scl);
    }
}

__device__ __forceinline__ void mma_compute_v(const uint32_t* As, const uint32_t* Bs,
                                              float acc[4][4][4], int warp_m, int warp_n, int lane){
    #pragma unroll
    for(int ks = 0; ks < 4; ks++){
        uint32_t a[4][4], bf[4][2];
        #pragma unroll
        for(int mi = 0; mi < 4; mi++){
            uint4 t = *(const uint4*)(As + (ks*8 + warp_m*4 + mi)*128 + lane*4);
            a[mi][0]=t.x; a[mi][1]=t.y; a[mi][2]=t.z; a[mi][3]=t.w;
        }
        #pragma unroll
        for(int ni = 0; ni < 4; ni++){
            uint2 t = *(const uint2*)(Bs + (ks*16 + warp_n*4 + ni)*64 + lane*2);
            bf[ni][0]=t.x; bf[ni][1]=t.y;
        }
        #pragma unroll
        for(int mi = 0; mi < 4; mi++)
            #pragma unroll
            for(int ni = 0; ni < 4; ni++)
                mma8(acc[mi][ni], a[mi], bf[ni]);
    }
}

#define GEMM_PRE() \
    extern __shared__ uint32_t smbuf[]; \
    uint32_t* Asb = smbuf; \
    uint32_t* Bsb = smbuf + 8192; \
    float acc[4][4][4]; \
    _Pragma("unroll") \
    for(int i=0;i<4;i++) _Pragma("unroll") for(int j=0;j<4;j++) _Pragma("unroll") for(int r=0;r<4;r++) acc[i][j][r]=0.f; \
    int tid = threadIdx.x; \
    int wid = tid >> 5, lane = tid & 31; \
    int warp_m = wid >> 2, warp_n = wid & 3; \
    int g = lane >> 2, tg = lane & 3; (void)g; (void)tg;

// ---------------- stage 1: spatial mean pool --------------------------------
__global__ void k_pool(const float* __restrict__ x){
    int id = blockIdx.x;
    int c = id & 255;
    int b = (id >> 8) & 3;
    int s = id >> 10;
    const float* p = x + (size_t)((s*BB+b)*CC + c) * HW;
    float sum = 0.f;
    for(int i = threadIdx.x; i < HW; i += 256) sum += p[i];
    __shared__ float red[8];
    #pragma unroll
    for(int o = 16; o > 0; o >>= 1) sum += __shfl_down_sync(0xffffffffu, sum, o);
    if((threadIdx.x & 31) == 0) red[threadIdx.x >> 5] = sum;
    __syncthreads();
    if(threadIdx.x == 0){
        float t = 0.f;
        #pragma unroll
        for(int i = 0; i < 8; i++) t += red[i];
        g_pooled[(b*SS + s)*CC + c] = t * (1.0f / HW);
    }
}

// ---------------- stage 2: importance MLP + softmax --------------------------
__global__ void k_imp(const float* __restrict__ iw1, const float* __restrict__ ib1,
                      const float* __restrict__ iw2, const float* __restrict__ ib2){
    __shared__ float h[BB][CC];
    __shared__ float lg[BB][SS];
    int t = threadIdx.x;
    for(int b = 0; b < BB; b++){
        float acc = ib1[t];
        const float4* pw = (const float4*)(iw1 + t * (SS*CC));
        const float4* pp = (const float4*)(g_pooled + b * (SS*CC));
        #pragma unroll 4
        for(int i = 0; i < (SS*CC)/4; i++){
            float4 a = pw[i], c = pp[i];
            acc += a.x*c.x + a.y*c.y + a.z*c.z + a.w*c.w;
        }
        h[b][t] = gelu_f(acc);
    }
    __syncthreads();
    if(t < BB*SS){
        int b = t / SS, s = t % SS;
        float acc = ib2[s];
        for(int c = 0; c < CC; c++) acc += h[b][c] * iw2[s*CC + c];
        lg[b][s] = acc;
    }
    __syncthreads();
    if(t < BB){
        float m  = fmaxf(lg[t][0], fmaxf(lg[t][1], lg[t][2]));
        float e0 = expf(lg[t][0]-m), e1 = expf(lg[t][1]-m), e2 = expf(lg[t][2]-m);
        float inv = 1.0f / (e0 + e1 + e2);
        g_wmix[t*SS+0] = e0*inv; g_wmix[t*SS+1] = e1*inv; g_wmix[t*SS+2] = e2*inv;
    }
}

// ---------------- stage 3: q/k/v projection ----------------------------------
__global__ __launch_bounds__(256,2) void k_projT(
    const float* __restrict__ x,
    const float* __restrict__ Wq, const float* __restrict__ bq, const float* __restrict__ bnq,
    const float* __restrict__ Wk_, const float* __restrict__ bk_, const float* __restrict__ bnk,
    const float* __restrict__ Wv, const float* __restrict__ bv, const float* __restrict__ bnv)
{
    int z = blockIdx.z;
    int which = z / 12;
    int s = (z % 12) >> 2;
    int b = z & 3;
    const float *W, *bias, *bn; float* out;
    if(which == 0){ W = Wq;  bias = bq;  bn = bnq; out = g_q; }
    else if(which == 1){ W = Wk_; bias = bk_; bn = bnk; out = g_k; }
    else { W = Wv; bias = bv; bn = bnv; out = g_v; }
    W += s * CC * CC;
    const float* X = x   + (size_t)(s*BB+b)*CC*HW;
    float*       O = out + (size_t)(s*BB+b)*CC*HW;
    int m0 = blockIdx.y * 128;
    int n0 = blockIdx.x * 128;

    GEMM_PRE();
    float4 ra[4], rb[4];
    fetchA(ra, W + (size_t)m0*CC, CC, tid);
    fetchB(rb, X + n0, HW, tid);
    storeA(Asb, ra, tid);
    storeB(Bsb, (const float*)rb, tid, 1.0f);
    __syncthreads();
    const int nk = CC/32;
    int cur = 0;
    for(int it = 0; it < nk; it++){
        bool more = (it+1 < nk);
        if(more){
            fetchA(ra, W + (size_t)m0*CC + (it+1)*32, CC, tid);
            fetchB(rb, X + (size_t)(it+1)*32*HW + n0, HW, tid);
        }
        mma_compute_v(Asb + cur*4096, Bsb + cur*4096, acc, warp_m, warp_n, lane);
        if(more){
            storeA(Asb + (cur^1)*4096, ra, tid);
            storeB(Bsb + (cur^1)*4096, (const float*)rb, tid, 1.0f);
        }
        __syncthreads();
        cur ^= 1;
    }
    #pragma unroll
    for(int mi = 0; mi < 4; mi++){
        int r0 = m0 + warp_m*64 + mi*16 + g;
        int r1 = r0 + 8;
        float sc0 = bn[(s*4+0)*CC+r0] * rsqrtf(bn[(s*4+3)*CC+r0] + EPSf);
        float sc1 = bn[(s*4+0)*CC+r1] * rsqrtf(bn[(s*4+3)*CC+r1] + EPSf);
        float be0 = bn[(s*4+1)*CC+r0], be1 = bn[(s*4+1)*CC+r1];
        float mu0 = bn[(s*4+2)*CC+r0], mu1 = bn[(s*4+2)*CC+r1];
        float bi0 = bias[s*CC+r0], bi1 = bias[s*CC+r1];
        #pragma unroll
        for(int ni = 0; ni < 4; ni++){
            int nc = n0 + warp_n*32 + ni*8 + tg*2;
            float2 o0, o1;
            o0.x = gelu_f((acc[mi][ni][0] + bi0 - mu0)*sc0 + be0);
            o0.y = gelu_f((acc[mi][ni][1] + bi0 - mu0)*sc0 + be0);
            o1.x = gelu_f((acc[mi][ni][2] + bi1 - mu1)*sc1 + be1);
            o1.y = gelu_f((acc[mi][ni][3] + bi1 - mu1)*sc1 + be1);
            *(float2*)&O[(size_t)r0*HW + nc] = o0;
            *(float2*)&O[(size_t)r1*HW + nc] = o1;
        }
    }
}

// ---------------- stage 4: attn_in projection --------------------------------
__global__ __launch_bounds__(256,2) void k_attninT(const float* __restrict__ aiw,
                                                   const float* __restrict__ aib)
{
    int z = blockIdx.z;
    int which = z / 12;
    int s = (z % 12) >> 2;
    int b = z & 3;
    const float* W = aiw + which * CC * CC;
    const float* bias = aib + which * CC;
    const float* Xg; float* Og;
    if(which == 0){ Xg = g_q; Og = g_qt; }
    else if(which == 1){ Xg = g_k; Og = g_kt; }
    else { Xg = g_v; Og = g_vt; }
    const float* X = Xg + (size_t)(s*BB+b)*CC*HW;
    float*       O = Og + (size_t)(s*BB+b)*CC*HW;
    int m0 = blockIdx.y * 128;
    int n0 = blockIdx.x * 128;

    GEMM_PRE();
    float4 ra[4], rb[4];
    fetchA(ra, W + (size_t)m0*CC, CC, tid);
    fetchB(rb, X + n0, HW, tid);
    storeA(Asb, ra, tid);
    storeB(Bsb, (const float*)rb, tid, 1.0f);
    __syncthreads();
    const int nk = CC/32;
    int cur = 0;
    for(int it = 0; it < nk; it++){
        bool more = (it+1 < nk);
        if(more){
            fetchA(ra, W + (size_t)m0*CC + (it+1)*32, CC, tid);
            fetchB(rb, X + (size_t)(it+1)*32*HW + n0, HW, tid);
        }
        mma_compute_v(Asb + cur*4096, Bsb + cur*4096, acc, warp_m, warp_n, lane);
        if(more){
            storeA(Asb + (cur^1)*4096, ra, tid);
            storeB(Bsb + (cur^1)*4096, (const float*)rb, tid, 1.0f);
        }
        __syncthreads();
        cur ^= 1;
    }
    #pragma unroll
    for(int mi = 0; mi < 4; mi++){
        int r0 = m0 + warp_m*64 + mi*16 + g;
        int r1 = r0 + 8;
        float bi0 = bias[r0], bi1 = bias[r1];
        #pragma unroll
        for(int ni = 0; ni < 4; ni++){
            int nc = n0 + warp_n*32 + ni*8 + tg*2;
            float2 o0, o1;
            o0.x = acc[mi][ni][0] + bi0; o0.y = acc[mi][ni][1] + bi0;
            o1.x = acc[mi][ni][2] + bi1; o1.y = acc[mi][ni][3] + bi1;
            *(float2*)&O[(size_t)r0*HW + nc] = o0;
            *(float2*)&O[(size_t)r1*HW + nc] = o1;
        }
    }
}

// ---------------- stage 5: tiny attention over S=3 ---------------------------
__global__ void k_attn(){
    int n = blockIdx.x * blockDim.x + threadIdx.x;
    int head = blockIdx.y;
    int b = n >> 12, p = n & 4095;
    int off0 = ((0*BB+b)*CC)*HW + p;
    int off1 = ((1*BB+b)*CC)*HW + p;
    int off2 = ((2*BB+b)*CC)*HW + p;
    int cbase = head * 32;

    float sc[3][3];
    #pragma unroll
    for(int i=0;i<3;i++){
        #pragma unroll
        for(int j=0;j<3;j++) sc[i][j]=0.f; }

    #pragma unroll 8
    for(int d = 0; d < 32; d++){
        int co = (cbase + d) * HW;
        float q0=g_qt[off0+co], q1=g_qt[off1+co], q2=g_qt[off2+co];
        float k0=g_kt[off0+co], k1=g_kt[off1+co], k2=g_kt[off2+co];
        sc[0][0]+=q0*k0; sc[0][1]+=q0*k1; sc[0][2]+=q0*k2;
        sc[1][0]+=q1*k0; sc[1][1]+=q1*k1; sc[1][2]+=q1*k2;
        sc[2][0]+=q2*k0; sc[2][1]+=q2*k1; sc[2][2]+=q2*k2;
    }
    const float scale = 0.17677669529663688f;
    float at[3][3];
    #pragma unroll
    for(int s_ = 0; s_ < 3; s_++){
        float a0 = sc[s_][0]*scale, a1 = sc[s_][1]*scale, a2 = sc[s_][2]*scale;
        float m = fmaxf(a0, fmaxf(a1, a2));
        float e0 = expf(a0-m), e1 = expf(a1-m), e2 = expf(a2-m);
        float inv = 1.0f / (e0+e1+e2);
        at[s_][0]=e0*inv; at[s_][1]=e1*inv; at[s_][2]=e2*inv;
    }
    #pragma unroll 8
    for(int d = 0; d < 32; d++){
        int co = (cbase + d) * HW;
        float v0=g_vt[off0+co], v1=g_vt[off1+co], v2=g_vt[off2+co];
        g_o[off0+co] = at[0][0]*v0 + at[0][1]*v1 + at[0][2]*v2;
        g_o[off1+co] = at[1][0]*v0 + at[1][1]*v1 + at[1][2]*v2;
        g_o[off2+co] = at[2][0]*v0 + at[2][1]*v1 + at[2][2]*v2;
    }
}

// ---------------- stage 6: attn_out + weighted s-combine (K=768) -------------
__global__ __launch_bounds__(256,2) void k_outT(const float* __restrict__ Wo,
                                                const float* __restrict__ bo)
{
    int b = blockIdx.z;
    int m0 = blockIdx.y * 128;
    int n0 = blockIdx.x * 128;
    float wmix[3] = { g_wmix[b*3+0], g_wmix[b*3+1], g_wmix[b*3+2] };

    GEMM_PRE();
    float4 ra[4], rb[4];
    fetchA(ra, Wo + (size_t)m0*CC, CC, tid);
    fetchB(rb, g_o + (size_t)(b*CC)*HW + n0, HW, tid);
    storeA(Asb, ra, tid);
    storeB(Bsb, (const float*)rb, tid, wmix[0]);
    __syncthreads();
    const int nk = (SS*CC)/32;
    int cur = 0;
    float scl_next = wmix[0];
    for(int it = 0; it < nk; it++){
        bool more = (it+1 < nk);
        if(more){
            int k0 = (it+1)*32;
            int s  = k0 >> 8;
            int cb2 = k0 & 255;
            scl_next = wmix[s];
            fetchA(ra, Wo + (size_t)m0*CC + cb2, CC, tid);
            fetchB(rb, g_o + (size_t)((s*BB+b)*CC + cb2)*HW + n0, HW, tid);
        }
        mma_compute_v(Asb + cur*4096, Bsb + cur*4096, acc, warp_m, warp_n, lane);
        if(more){
            storeA(Asb + (cur^1)*4096, ra, tid);
            storeB(Bsb + (cur^1)*4096, (const float*)rb, tid, scl_next);
        }
        __syncthreads();
        cur ^= 1;
    }
    #pragma unroll
    for(int mi = 0; mi < 4; mi++){
        int r0 = m0 + warp_m*64 + mi*16 + g;
        int r1 = r0 + 8;
        float bi0 = bo[r0], bi1 = bo[r1];
        #pragma unroll
        for(int ni = 0; ni < 4; ni++){
            int nc = n0 + warp_n*32 + ni*8 + tg*2;
            float2 o0, o1;
            o0.x = acc[mi][ni][0] + bi0; o0.y = acc[mi][ni][1] + bi0;
            o1.x = acc[mi][ni][2] + bi1; o1.y = acc[mi][ni][3] + bi1;
            *(float2*)&g_integr[(size_t)(b*CC+r0)*HW + nc] = o0;
            *(float2*)&g_integr[(size_t)(b*CC+r1)*HW + nc] = o1;
        }
    }
}

// ---------------- stage 7: 3x3 conv as GEMM (K=2304) -------------------------
__device__ __forceinline__ void fetchB_conv(float v[16], int b, int k0, int n0, int tid){
    int k = tid >> 3, nb = (tid & 7) * 16;
    int kkg = k0 + k;
    int c  = kkg / 9;
    int r9 = kkg - c*9;
    int kh = r9 / 3, kw = r9 - kh*3;
    const float* src = g_integr + (size_t)(b*CC + c)*HW;
    #pragma unroll
    for(int j = 0; j < 16; j++){
        int pix = n0 + nb + j;
        int hh = (pix >> 6) + kh - 1;
        int ww = (pix & 63) + kw - 1;
        float val = 0.f;
        if((unsigned)hh < 64u && (unsigned)ww < 64u) val = src[hh*64 + ww];
        v[j] = val;
    }
}

__global__ __launch_bounds__(256,2) void k_convT(const float* __restrict__ Wc,
                                                 const float* __restrict__ b1,
                                                 const float* __restrict__ opbn)
{
    int b = blockIdx.z;
    int m0 = blockIdx.y * 128;
    int n0 = blockIdx.x * 128;

    GEMM_PRE();
    float4 ra[4];
    float rv[16];
    fetchA(ra, Wc + (size_t)m0*(CC*9), CC*9, tid);
    fetchB_conv(rv, b, 0, n0, tid);
    storeA(Asb, ra, tid);
    storeB(Bsb, rv, tid, 1.0f);
    __syncthreads();
    const int nk = (CC*9)/32;
    int cur = 0;
    for(int it = 0; it < nk; it++){
        bool more = (it+1 < nk);
        if(more){
            fetchA(ra, Wc + (size_t)m0*(CC*9) + (it+1)*32, CC*9, tid);
            fetchB_conv(rv, b, (it+1)*32, n0, tid);
        }
        mma_compute_v(Asb + cur*4096, Bsb + cur*4096, acc, warp_m, warp_n, lane);
        if(more){
            storeA(Asb + (cur^1)*4096, ra, tid);
            storeB(Bsb + (cur^1)*4096, rv, tid, 1.0f);
        }
        __syncthreads();
        cur ^= 1;
    }
    #pragma unroll
    for(int mi = 0; mi < 4; mi++){
        int r0 = m0 + warp_m*64 + mi*16 + g;
        int r1 = r0 + 8;
        float sc0 = opbn[0*CC+r0] * rsqrtf(opbn[3*CC+r0] + EPSf);
        float sc1 = opbn[0*CC+r1] * rsqrtf(opbn[3*CC+r1] + EPSf);
        float be0 = opbn[1*CC+r0], be1 = opbn[1*CC+r1];
        float mu0 = opbn[2*CC+r0], mu1 = opbn[2*CC+r1];
        float bi0 = b1[r0], bi1 = b1[r1];
        #pragma unroll
        for(int ni = 0; ni < 4; ni++){
            int nc = n0 + warp_n*32 + ni*8 + tg*2;
            float2 o0, o1;
            o0.x = gelu_f((acc[mi][ni][0] + bi0 - mu0)*sc0 + be0);
            o0.y = gelu_f((acc[mi][ni][1] + bi0 - mu0)*sc0 + be0);
            o1.x = gelu_f((acc[mi][ni][2] + bi1 - mu1)*sc1 + be1);
            o1.y = gelu_f((acc[mi][ni][3] + bi1 - mu1)*sc1 + be1);
            *(float2*)&g_y2[(size_t)(b*CC+r0)*HW + nc] = o0;
            *(float2*)&g_y2[(size_t)(b*CC+r1)*HW + nc] = o1;
        }
    }
}

// ---------------- stage 8: final 1x1 + residual ------------------------------
__global__ __launch_bounds__(256,2) void k_finalT(const float* __restrict__ W2,
                                                  const float* __restrict__ b2,
                                                  const float* __restrict__ x,
                                                  float* __restrict__ out)
{
    int b = blockIdx.z;
    int m0 = blockIdx.y * 128;
    int n0 = blockIdx.x * 128;

    GEMM_PRE();
    float4 ra[4], rb[4];
    fetchA(ra, W2 + (size_t)m0*CC, CC, tid);
    fetchB(rb, g_y2 + (size_t)(b*CC)*HW + n0, HW, tid);
    storeA(Asb, ra, tid);
    storeB(Bsb, (const float*)rb, tid, 1.0f);
    __syncthreads();
    const int nk = CC/32;
    int cur = 0;
    for(int it = 0; it < nk; it++){
        bool more = (it+1 < nk);
        if(more){
            fetchA(ra, W2 + (size_t)m0*CC + (it+1)*32, CC, tid);
            fetchB(rb, g_y2 + (size_t)(b*CC + (it+1)*32)*HW + n0, HW, tid);
        }
        mma_compute_v(Asb + cur*4096, Bsb + cur*4096, acc, warp_m, warp_n, lane);
        if(more){
            storeA(Asb + (cur^1)*4096, ra, tid);
            storeB(Bsb + (cur^1)*4096, (const float*)rb, tid, 1.0f);
        }
        __syncthreads();
        cur ^= 1;
    }
    #pragma unroll
    for(int mi = 0; mi < 4; mi++){
        int r0 = m0 + warp_m*64 + mi*16 + g;
        int r1 = r0 + 8;
        float bi0 = b2[r0], bi1 = b2[r1];
        const float* res0 = x + (size_t)((1*BB+b)*CC + r0)*HW;
        const float* res1 = x + (size_t)((1*BB+b)*CC + r1)*HW;
        #pragma unroll
        for(int ni = 0; ni < 4; ni++){
            int nc = n0 + warp_n*32 + ni*8 + tg*2;
            float2 a0 = *(const float2*)&res0[nc];
            float2 a1 = *(const float2*)&res1[nc];
            float2 o0, o1;
            o0.x = acc[mi][ni][0] + bi0 + a0.x; o0.y = acc[mi][ni][1] + bi0 + a0.y;
            o1.x = acc[mi][ni][2] + bi1 + a1.x; o1.y = acc[mi][ni][3] + bi1 + a1.y;
            *(float2*)&out[(size_t)(b*CC+r0)*HW + nc] = o0;
            *(float2*)&out[(size_t)(b*CC+r1)*HW + nc] = o1;
        }
    }
}

// ---------------- launcher ---------------------------------------------------
extern "C" void kernel_launch(void* const* d_in, const int* in_sizes, int n_in,
                              void* d_out, int out_size)
{
    (void)in_sizes; (void)n_in; (void)out_size;
    const float* x   = (const float*)d_in[0];
    const float* Wq  = (const float*)d_in[1];
    const float* bq  = (const float*)d_in[2];
    const float* bnq = (const float*)d_in[3];
    const float* Wk_ = (const float*)d_in[4];
    const float* bk_ = (const float*)d_in[5];
    const float* bnk = (const float*)d_in[6];
    const float* Wv  = (const float*)d_in[7];
    const float* bv  = (const float*)d_in[8];
    const float* bnv = (const float*)d_in[9];
    const float* iw1 = (const float*)d_in[10];
    const float* ib1 = (const float*)d_in[11];
    const float* iw2 = (const float*)d_in[12];
    const float* ib2 = (const float*)d_in[13];
    const float* aiw = (const float*)d_in[14];
    const float* aib = (const float*)d_in[15];
    const float* aow = (const float*)d_in[16];
    const float* aob = (const float*)d_in[17];
    const float* cw  = (const float*)d_in[18];
    const float* cb1 = (const float*)d_in[19];
    const float* cbn = (const float*)d_in[20];
    const float* w2  = (const float*)d_in[21];
    const float* b2  = (const float*)d_in[22];
    float* out = (float*)d_out;

    const int SMEM = 64 * 1024;
    cudaFuncSetAttribute(k_projT,   cudaFuncAttributeMaxDynamicSharedMemorySize, SMEM);
    cudaFuncSetAttribute(k_attninT, cudaFuncAttributeMaxDynamicSharedMemorySize, SMEM);
    cudaFuncSetAttribute(k_outT,    cudaFuncAttributeMaxDynamicSharedMemorySize, SMEM);
    cudaFuncSetAttribute(k_convT,   cudaFuncAttributeMaxDynamicSharedMemorySize, SMEM);
    cudaFuncSetAttribute(k_finalT,  cudaFuncAttributeMaxDynamicSharedMemorySize, SMEM);

    k_pool<<<SS*BB*CC, 256>>>(x);
    k_imp<<<1, 256>>>(iw1, ib1, iw2, ib2);
    k_projT<<<dim3(32,2,36), 256, SMEM>>>(x, Wq,bq,bnq, Wk_,bk_,bnk, Wv,bv,bnv);
    k_attninT<<<dim3(32,2,36), 256, SMEM>>>(aiw, aib);
    k_attn<<<dim3(64,8), 256>>>();
    k_outT<<<dim3(32,2,4), 256, SMEM>>>(aow, aob);
    k_convT<<<dim3(32,2,4), 256, SMEM>>>(cw, cb1, cbn);
    k_finalT<<<dim3(32,2,4), 256, SMEM>>>(w2, b2, x, out);
}

// round 5
// speedup vs baseline: 1.5617x; 1.5617x over previous
#include <cuda_runtime.h>
#include <cuda_bf16.h>
#include <cstdint>
#include <math.h>

#define SS 3
#define BB 4
#define CC 256
#define HW 4096
#define EPSf 1e-5f

// ---------------- scratch ----------------------------------------------------
__device__ float g_pooled[BB*SS*CC];
__device__ float g_wmix[BB*SS];
__device__ float g_q [SS*BB*CC*HW];
__device__ float g_k [SS*BB*CC*HW];
__device__ float g_v [SS*BB*CC*HW];
__device__ float g_qt[SS*BB*CC*HW];
__device__ float g_kt[SS*BB*CC*HW];
__device__ float g_vt[SS*BB*CC*HW];
__device__ float g_o [SS*BB*CC*HW];
__device__ float g_integr[BB*CC*HW];
__device__ float g_y2[BB*CC*HW];

__device__ __forceinline__ float gelu_f(float x){
    return 0.5f * x * (1.0f + erff(x * 0.70710678118654752f));
}
__device__ __forceinline__ uint32_t pkbf(float lo, float hi){
    __nv_bfloat162 h = __float22bfloat162_rn(make_float2(lo, hi));
    return *(uint32_t*)&h;
}
__device__ __forceinline__ void mma16(float c[4], const uint32_t a[4], const uint32_t b[2]){
    asm volatile(
        "mma.sync.aligned.m16n8k16.row.col.f32.bf16.bf16.f32 "
        "{%0,%1,%2,%3}, {%4,%5,%6,%7}, {%8,%9}, {%0,%1,%2,%3};"
        : "+f"(c[0]), "+f"(c[1]), "+f"(c[2]), "+f"(c[3])
        : "r"(a[0]), "r"(a[1]), "r"(a[2]), "r"(a[3]), "r"(b[0]), "r"(b[1]));
}

// ---------------- GEMM building blocks ---------------------------------------
// CTA tile 128x128, BK=32 (16 bf16x2 pairs), 256 threads = 8 warps (2M x 4N),
// warp tile 64x32.  SMEM (per buffer): As[16][128] u32, pair kp at
// As[kp][(m+8kp)&127] = {A[m][2kp], A[m][2kp+1]};  Bs[kp][(n+8kp)&127] =
// {X[2kp][n], X[2kp+1][n]}.  Fragment loads conflict-free (bank = g+8*tg).

__device__ __forceinline__ void fetchA_pk(uint32_t rp[8], const float* Wt, int lda, int tid){
    int m = tid >> 1, kh = (tid & 1) * 16;
    const float4* s = (const float4*)(Wt + (size_t)m*lda + kh);
    float4 v0=s[0], v1=s[1], v2=s[2], v3=s[3];
    rp[0]=pkbf(v0.x,v0.y); rp[1]=pkbf(v0.z,v0.w);
    rp[2]=pkbf(v1.x,v1.y); rp[3]=pkbf(v1.z,v1.w);
    rp[4]=pkbf(v2.x,v2.y); rp[5]=pkbf(v2.z,v2.w);
    rp[6]=pkbf(v3.x,v3.y); rp[7]=pkbf(v3.z,v3.w);
}
__device__ __forceinline__ void storeA_pk(uint32_t* As, const uint32_t rp[8], int tid){
    int m = tid >> 1, kb = (tid & 1) * 8;
    #pragma unroll
    for(int i = 0; i < 8; i++){
        int kp = kb + i;
        As[kp*128 + ((m + 8*kp) & 127)] = rp[i];
    }
}
__device__ __forceinline__ void fetchB_pk(uint32_t rp[8], const float* Xt, int stride, int tid, float scl){
    int kp = tid >> 4, nb = (tid & 15) * 8;
    const float4* s0 = (const float4*)(Xt + (size_t)(2*kp)*stride + nb);
    const float4* s1 = (const float4*)(Xt + (size_t)(2*kp+1)*stride + nb);
    float4 a0=s0[0], a1=s0[1];
    float4 b0=s1[0], b1=s1[1];
    rp[0]=pkbf(a0.x*scl, b0.x*scl); rp[1]=pkbf(a0.y*scl, b0.y*scl);
    rp[2]=pkbf(a0.z*scl, b0.z*scl); rp[3]=pkbf(a0.w*scl, b0.w*scl);
    rp[4]=pkbf(a1.x*scl, b1.x*scl); rp[5]=pkbf(a1.y*scl, b1.y*scl);
    rp[6]=pkbf(a1.z*scl, b1.z*scl); rp[7]=pkbf(a1.w*scl, b1.w*scl);
}
__device__ __forceinline__ void storeB_pk(uint32_t* Bs, const uint32_t rp[8], int tid){
    int kp = tid >> 4, nb = (tid & 15) * 8;
    #pragma unroll
    for(int j = 0; j < 8; j++){
        Bs[kp*128 + ((nb + j + 8*kp) & 127)] = rp[j];
    }
}

__device__ __forceinline__ void mma_compute_bf(const uint32_t* As, const uint32_t* Bs,
                                               float acc[4][4][4], int warp_m, int warp_n, int lane){
    int g = lane >> 2, tg = lane & 3;
    #pragma unroll
    for(int ks = 0; ks < 2; ks++){
        int kp1 = ks*8 + tg, kp2 = kp1 + 4;
        uint32_t a[4][4], bf[4][2];
        #pragma unroll
        for(int mi = 0; mi < 4; mi++){
            int m = warp_m*64 + mi*16 + g;
            a[mi][0] = As[kp1*128 + ((m     + 8*kp1) & 127)];
            a[mi][1] = As[kp1*128 + ((m + 8 + 8*kp1) & 127)];
            a[mi][2] = As[kp2*128 + ((m     + 8*kp2) & 127)];
            a[mi][3] = As[kp2*128 + ((m + 8 + 8*kp2) & 127)];
        }
        #pragma unroll
        for(int ni = 0; ni < 4; ni++){
            int n = warp_n*32 + ni*8 + g;
            bf[ni][0] = Bs[kp1*128 + ((n + 8*kp1) & 127)];
            bf[ni][1] = Bs[kp2*128 + ((n + 8*kp2) & 127)];
        }
        #pragma unroll
        for(int mi = 0; mi < 4; mi++)
            #pragma unroll
            for(int ni = 0; ni < 4; ni++)
                mma16(acc[mi][ni], a[mi], bf[ni]);
    }
}

#define GEMM_PRE() \
    __shared__ uint32_t Asb[2][16*128]; \
    __shared__ uint32_t Bsb[2][16*128]; \
    float acc[4][4][4]; \
    _Pragma("unroll") \
    for(int i=0;i<4;i++) _Pragma("unroll") for(int j=0;j<4;j++) _Pragma("unroll") for(int r=0;r<4;r++) acc[i][j][r]=0.f; \
    int tid = threadIdx.x; \
    int wid = tid >> 5, lane = tid & 31; \
    int warp_m = wid >> 2, warp_n = wid & 3; \
    int g = lane >> 2, tg = lane & 3; (void)g; (void)tg;

// ---------------- stage 1: spatial mean pool --------------------------------
__global__ void k_pool(const float* __restrict__ x){
    int id = blockIdx.x;
    int c = id & 255;
    int b = (id >> 8) & 3;
    int s = id >> 10;
    const float* p = x + (size_t)((s*BB+b)*CC + c) * HW;
    float sum = 0.f;
    for(int i = threadIdx.x; i < HW; i += 256) sum += p[i];
    __shared__ float red[8];
    #pragma unroll
    for(int o = 16; o > 0; o >>= 1) sum += __shfl_down_sync(0xffffffffu, sum, o);
    if((threadIdx.x & 31) == 0) red[threadIdx.x >> 5] = sum;
    __syncthreads();
    if(threadIdx.x == 0){
        float t = 0.f;
        #pragma unroll
        for(int i = 0; i < 8; i++) t += red[i];
        g_pooled[(b*SS + s)*CC + c] = t * (1.0f / HW);
    }
}

// ---------------- stage 2: importance MLP + softmax --------------------------
__global__ void k_imp(const float* __restrict__ iw1, const float* __restrict__ ib1,
                      const float* __restrict__ iw2, const float* __restrict__ ib2){
    __shared__ float h[BB][CC];
    __shared__ float lg[BB][SS];
    int t = threadIdx.x;
    for(int b = 0; b < BB; b++){
        float acc = ib1[t];
        const float4* pw = (const float4*)(iw1 + t * (SS*CC));
        const float4* pp = (const float4*)(g_pooled + b * (SS*CC));
        #pragma unroll 4
        for(int i = 0; i < (SS*CC)/4; i++){
            float4 a = pw[i], c = pp[i];
            acc += a.x*c.x + a.y*c.y + a.z*c.z + a.w*c.w;
        }
        h[b][t] = gelu_f(acc);
    }
    __syncthreads();
    if(t < BB*SS){
        int b = t / SS, s = t % SS;
        float acc = ib2[s];
        for(int c = 0; c < CC; c++) acc += h[b][c] * iw2[s*CC + c];
        lg[b][s] = acc;
    }
    __syncthreads();
    if(t < BB){
        float m  = fmaxf(lg[t][0], fmaxf(lg[t][1], lg[t][2]));
        float e0 = expf(lg[t][0]-m), e1 = expf(lg[t][1]-m), e2 = expf(lg[t][2]-m);
        float inv = 1.0f / (e0 + e1 + e2);
        g_wmix[t*SS+0] = e0*inv; g_wmix[t*SS+1] = e1*inv; g_wmix[t*SS+2] = e2*inv;
    }
}

// ---------------- stage 3: q/k/v projection ----------------------------------
__global__ __launch_bounds__(256,2) void k_projT(
    const float* __restrict__ x,
    const float* __restrict__ Wq, const float* __restrict__ bq, const float* __restrict__ bnq,
    const float* __restrict__ Wk_, const float* __restrict__ bk_, const float* __restrict__ bnk,
    const float* __restrict__ Wv, const float* __restrict__ bv, const float* __restrict__ bnv)
{
    int z = blockIdx.z;
    int which = z / 12;
    int s = (z % 12) >> 2;
    int b = z & 3;
    const float *W, *bias, *bn; float* out;
    if(which == 0){ W = Wq;  bias = bq;  bn = bnq; out = g_q; }
    else if(which == 1){ W = Wk_; bias = bk_; bn = bnk; out = g_k; }
    else { W = Wv; bias = bv; bn = bnv; out = g_v; }
    W += s * CC * CC;
    const float* X = x   + (size_t)(s*BB+b)*CC*HW;
    float*       O = out + (size_t)(s*BB+b)*CC*HW;
    int m0 = blockIdx.y * 128;
    int n0 = blockIdx.x * 128;

    GEMM_PRE();
    uint32_t ra[8], rb[8];
    fetchA_pk(ra, W + (size_t)m0*CC, CC, tid);
    fetchB_pk(rb, X + n0, HW, tid, 1.0f);
    storeA_pk(Asb[0], ra, tid);
    storeB_pk(Bsb[0], rb, tid);
    __syncthreads();
    const int nk = CC/32;
    int cur = 0;
    for(int it = 0; it < nk; it++){
        bool more = (it+1 < nk);
        if(more){
            fetchA_pk(ra, W + (size_t)m0*CC + (it+1)*32, CC, tid);
            fetchB_pk(rb, X + (size_t)(it+1)*32*HW + n0, HW, tid, 1.0f);
        }
        mma_compute_bf(Asb[cur], Bsb[cur], acc, warp_m, warp_n, lane);
        if(more){
            storeA_pk(Asb[cur^1], ra, tid);
            storeB_pk(Bsb[cur^1], rb, tid);
        }
        __syncthreads();
        cur ^= 1;
    }
    #pragma unroll
    for(int mi = 0; mi < 4; mi++){
        int r0 = m0 + warp_m*64 + mi*16 + g;
        int r1 = r0 + 8;
        float sc0 = bn[(s*4+0)*CC+r0] * rsqrtf(bn[(s*4+3)*CC+r0] + EPSf);
        float sc1 = bn[(s*4+0)*CC+r1] * rsqrtf(bn[(s*4+3)*CC+r1] + EPSf);
        float be0 = bn[(s*4+1)*CC+r0], be1 = bn[(s*4+1)*CC+r1];
        float mu0 = bn[(s*4+2)*CC+r0], mu1 = bn[(s*4+2)*CC+r1];
        float bi0 = bias[s*CC+r0], bi1 = bias[s*CC+r1];
        #pragma unroll
        for(int ni = 0; ni < 4; ni++){
            int nc = n0 + warp_n*32 + ni*8 + tg*2;
            float2 o0, o1;
            o0.x = gelu_f((acc[mi][ni][0] + bi0 - mu0)*sc0 + be0);
            o0.y = gelu_f((acc[mi][ni][1] + bi0 - mu0)*sc0 + be0);
            o1.x = gelu_f((acc[mi][ni][2] + bi1 - mu1)*sc1 + be1);
            o1.y = gelu_f((acc[mi][ni][3] + bi1 - mu1)*sc1 + be1);
            *(float2*)&O[(size_t)r0*HW + nc] = o0;
            *(float2*)&O[(size_t)r1*HW + nc] = o1;
        }
    }
}

// ---------------- stage 4: attn_in projection --------------------------------
__global__ __launch_bounds__(256,2) void k_attninT(const float* __restrict__ aiw,
                                                   const float* __restrict__ aib)
{
    int z = blockIdx.z;
    int which = z / 12;
    int s = (z % 12) >> 2;
    int b = z & 3;
    const float* W = aiw + which * CC * CC;
    const float* bias = aib + which * CC;
    const float* Xg; float* Og;
    if(which == 0){ Xg = g_q; Og = g_qt; }
    else if(which == 1){ Xg = g_k; Og = g_kt; }
    else { Xg = g_v; Og = g_vt; }
    const float* X = Xg + (size_t)(s*BB+b)*CC*HW;
    float*       O = Og + (size_t)(s*BB+b)*CC*HW;
    int m0 = blockIdx.y * 128;
    int n0 = blockIdx.x * 128;

    GEMM_PRE();
    uint32_t ra[8], rb[8];
    fetchA_pk(ra, W + (size_t)m0*CC, CC, tid);
    fetchB_pk(rb, X + n0, HW, tid, 1.0f);
    storeA_pk(Asb[0], ra, tid);
    storeB_pk(Bsb[0], rb, tid);
    __syncthreads();
    const int nk = CC/32;
    int cur = 0;
    for(int it = 0; it < nk; it++){
        bool more = (it+1 < nk);
        if(more){
            fetchA_pk(ra, W + (size_t)m0*CC + (it+1)*32, CC, tid);
            fetchB_pk(rb, X + (size_t)(it+1)*32*HW + n0, HW, tid, 1.0f);
        }
        mma_compute_bf(Asb[cur], Bsb[cur], acc, warp_m, warp_n, lane);
        if(more){
            storeA_pk(Asb[cur^1], ra, tid);
            storeB_pk(Bsb[cur^1], rb, tid);
        }
        __syncthreads();
        cur ^= 1;
    }
    #pragma unroll
    for(int mi = 0; mi < 4; mi++){
        int r0 = m0 + warp_m*64 + mi*16 + g;
        int r1 = r0 + 8;
        float bi0 = bias[r0], bi1 = bias[r1];
        #pragma unroll
        for(int ni = 0; ni < 4; ni++){
            int nc = n0 + warp_n*32 + ni*8 + tg*2;
            float2 o0, o1;
            o0.x = acc[mi][ni][0] + bi0; o0.y = acc[mi][ni][1] + bi0;
            o1.x = acc[mi][ni][2] + bi1; o1.y = acc[mi][ni][3] + bi1;
            *(float2*)&O[(size_t)r0*HW + nc] = o0;
            *(float2*)&O[(size_t)r1*HW + nc] = o1;
        }
    }
}

// ---------------- stage 5: tiny attention over S=3 ---------------------------
__global__ void k_attn(){
    int n = blockIdx.x * blockDim.x + threadIdx.x;
    int head = blockIdx.y;
    int b = n >> 12, p = n & 4095;
    int off0 = ((0*BB+b)*CC)*HW + p;
    int off1 = ((1*BB+b)*CC)*HW + p;
    int off2 = ((2*BB+b)*CC)*HW + p;
    int cbase = head * 32;

    float sc[3][3];
    #pragma unroll
    for(int i=0;i<3;i++){
        #pragma unroll
        for(int j=0;j<3;j++) sc[i][j]=0.f; }

    #pragma unroll 8
    for(int d = 0; d < 32; d++){
        int co = (cbase + d) * HW;
        float q0=g_qt[off0+co], q1=g_qt[off1+co], q2=g_qt[off2+co];
        float k0=g_kt[off0+co], k1=g_kt[off1+co], k2=g_kt[off2+co];
        sc[0][0]+=q0*k0; sc[0][1]+=q0*k1; sc[0][2]+=q0*k2;
        sc[1][0]+=q1*k0; sc[1][1]+=q1*k1; sc[1][2]+=q1*k2;
        sc[2][0]+=q2*k0; sc[2][1]+=q2*k1; sc[2][2]+=q2*k2;
    }
    const float scale = 0.17677669529663688f;
    float at[3][3];
    #pragma unroll
    for(int s_ = 0; s_ < 3; s_++){
        float a0 = sc[s_][0]*scale, a1 = sc[s_][1]*scale, a2 = sc[s_][2]*scale;
        float m = fmaxf(a0, fmaxf(a1, a2));
        float e0 = expf(a0-m), e1 = expf(a1-m), e2 = expf(a2-m);
        float inv = 1.0f / (e0+e1+e2);
        at[s_][0]=e0*inv; at[s_][1]=e1*inv; at[s_][2]=e2*inv;
    }
    #pragma unroll 8
    for(int d = 0; d < 32; d++){
        int co = (cbase + d) * HW;
        float v0=g_vt[off0+co], v1=g_vt[off1+co], v2=g_vt[off2+co];
        g_o[off0+co] = at[0][0]*v0 + at[0][1]*v1 + at[0][2]*v2;
        g_o[off1+co] = at[1][0]*v0 + at[1][1]*v1 + at[1][2]*v2;
        g_o[off2+co] = at[2][0]*v0 + at[2][1]*v1 + at[2][2]*v2;
    }
}

// ---------------- stage 6: attn_out + weighted s-combine (K=768) -------------
__global__ __launch_bounds__(256,2) void k_outT(const float* __restrict__ Wo,
                                                const float* __restrict__ bo)
{
    int b = blockIdx.z;
    int m0 = blockIdx.y * 128;
    int n0 = blockIdx.x * 128;
    float wmix[3] = { g_wmix[b*3+0], g_wmix[b*3+1], g_wmix[b*3+2] };

    GEMM_PRE();
    uint32_t ra[8], rb[8];
    fetchA_pk(ra, Wo + (size_t)m0*CC, CC, tid);
    fetchB_pk(rb, g_o + (size_t)(b*CC)*HW + n0, HW, tid, wmix[0]);
    storeA_pk(Asb[0], ra, tid);
    storeB_pk(Bsb[0], rb, tid);
    __syncthreads();
    const int nk = (SS*CC)/32;
    int cur = 0;
    for(int it = 0; it < nk; it++){
        bool more = (it+1 < nk);
        if(more){
            int k0 = (it+1)*32;
            int s  = k0 >> 8;
            int cb2 = k0 & 255;
            fetchA_pk(ra, Wo + (size_t)m0*CC + cb2, CC, tid);
            fetchB_pk(rb, g_o + (size_t)((s*BB+b)*CC + cb2)*HW + n0, HW, tid, wmix[s]);
        }
        mma_compute_bf(Asb[cur], Bsb[cur], acc, warp_m, warp_n, lane);
        if(more){
            storeA_pk(Asb[cur^1], ra, tid);
            storeB_pk(Bsb[cur^1], rb, tid);
        }
        __syncthreads();
        cur ^= 1;
    }
    #pragma unroll
    for(int mi = 0; mi < 4; mi++){
        int r0 = m0 + warp_m*64 + mi*16 + g;
        int r1 = r0 + 8;
        float bi0 = bo[r0], bi1 = bo[r1];
        #pragma unroll
        for(int ni = 0; ni < 4; ni++){
            int nc = n0 + warp_n*32 + ni*8 + tg*2;
            float2 o0, o1;
            o0.x = acc[mi][ni][0] + bi0; o0.y = acc[mi][ni][1] + bi0;
            o1.x = acc[mi][ni][2] + bi1; o1.y = acc[mi][ni][3] + bi1;
            *(float2*)&g_integr[(size_t)(b*CC+r0)*HW + nc] = o0;
            *(float2*)&g_integr[(size_t)(b*CC+r1)*HW + nc] = o1;
        }
    }
}

// ---------------- stage 7: 3x3 conv as GEMM (K=2304) -------------------------
__device__ __forceinline__ void fetchB_conv_pk(uint32_t rp[8], int b, int k0, int n0, int tid){
    int kp = tid >> 4, nb = (tid & 15) * 8;
    float v[2][8];
    #pragma unroll
    for(int half = 0; half < 2; half++){
        int kkg = k0 + 2*kp + half;
        int c  = kkg / 9;
        int r9 = kkg - c*9;
        int kh = r9 / 3, kw = r9 - kh*3;
        const float* src = g_integr + (size_t)(b*CC + c)*HW;
        #pragma unroll
        for(int j = 0; j < 8; j++){
            int pix = n0 + nb + j;
            int hh = (pix >> 6) + kh - 1;
            int ww = (pix & 63) + kw - 1;
            float val = 0.f;
            if((unsigned)hh < 64u && (unsigned)ww < 64u) val = src[hh*64 + ww];
            v[half][j] = val;
        }
    }
    #pragma unroll
    for(int j = 0; j < 8; j++) rp[j] = pkbf(v[0][j], v[1][j]);
}

__global__ __launch_bounds__(256,2) void k_convT(const float* __restrict__ Wc,
                                                 const float* __restrict__ b1,
                                                 const float* __restrict__ opbn)
{
    int b = blockIdx.z;
    int m0 = blockIdx.y * 128;
    int n0 = blockIdx.x * 128;

    GEMM_PRE();
    uint32_t ra[8], rb[8];
    fetchA_pk(ra, Wc + (size_t)m0*(CC*9), CC*9, tid);
    fetchB_conv_pk(rb, b, 0, n0, tid);
    storeA_pk(Asb[0], ra, tid);
    storeB_pk(Bsb[0], rb, tid);
    __syncthreads();
    const int nk = (CC*9)/32;
    int cur = 0;
    for(int it = 0; it < nk; it++){
        bool more = (it+1 < nk);
        if(more){
            fetchA_pk(ra, Wc + (size_t)m0*(CC*9) + (it+1)*32, CC*9, tid);
            fetchB_conv_pk(rb, b, (it+1)*32, n0, tid);
        }
        mma_compute_bf(Asb[cur], Bsb[cur], acc, warp_m, warp_n, lane);
        if(more){
            storeA_pk(Asb[cur^1], ra, tid);
            storeB_pk(Bsb[cur^1], rb, tid);
        }
        __syncthreads();
        cur ^= 1;
    }
    #pragma unroll
    for(int mi = 0; mi < 4; mi++){
        int r0 = m0 + warp_m*64 + mi*16 + g;
        int r1 = r0 + 8;
        float sc0 = opbn[0*CC+r0] * rsqrtf(opbn[3*CC+r0] + EPSf);
        float sc1 = opbn[0*CC+r1] * rsqrtf(opbn[3*CC+r1] + EPSf);
        float be0 = opbn[1*CC+r0], be1 = opbn[1*CC+r1];
        float mu0 = opbn[2*CC+r0], mu1 = opbn[2*CC+r1];
        float bi0 = b1[r0], bi1 = b1[r1];
        #pragma unroll
        for(int ni = 0; ni < 4; ni++){
            int nc = n0 + warp_n*32 + ni*8 + tg*2;
            float2 o0, o1;
            o0.x = gelu_f((acc[mi][ni][0] + bi0 - mu0)*sc0 + be0);
            o0.y = gelu_f((acc[mi][ni][1] + bi0 - mu0)*sc0 + be0);
            o1.x = gelu_f((acc[mi][ni][2] + bi1 - mu1)*sc1 + be1);
            o1.y = gelu_f((acc[mi][ni][3] + bi1 - mu1)*sc1 + be1);
            *(float2*)&g_y2[(size_t)(b*CC+r0)*HW + nc] = o0;
            *(float2*)&g_y2[(size_t)(b*CC+r1)*HW + nc] = o1;
        }
    }
}

// ---------------- stage 8: final 1x1 + residual ------------------------------
__global__ __launch_bounds__(256,2) void k_finalT(const float* __restrict__ W2,
                                                  const float* __restrict__ b2,
                                                  const float* __restrict__ x,
                                                  float* __restrict__ out)
{
    int b = blockIdx.z;
    int m0 = blockIdx.y * 128;
    int n0 = blockIdx.x * 128;

    GEMM_PRE();
    uint32_t ra[8], rb[8];
    fetchA_pk(ra, W2 + (size_t)m0*CC, CC, tid);
    fetchB_pk(rb, g_y2 + (size_t)(b*CC)*HW + n0, HW, tid, 1.0f);
    storeA_pk(Asb[0], ra, tid);
    storeB_pk(Bsb[0], rb, tid);
    __syncthreads();
    const int nk = CC/32;
    int cur = 0;
    for(int it = 0; it < nk; it++){
        bool more = (it+1 < nk);
        if(more){
            fetchA_pk(ra, W2 + (size_t)m0*CC + (it+1)*32, CC, tid);
            fetchB_pk(rb, g_y2 + (size_t)(b*CC + (it+1)*32)*HW + n0, HW, tid, 1.0f);
        }
        mma_compute_bf(Asb[cur], Bsb[cur], acc, warp_m, warp_n, lane);
        if(more){
            storeA_pk(Asb[cur^1], ra, tid);
            storeB_pk(Bsb[cur^1], rb, tid);
        }
        __syncthreads();
        cur ^= 1;
    }
    #pragma unroll
    for(int mi = 0; mi < 4; mi++){
        int r0 = m0 + warp_m*64 + mi*16 + g;
        int r1 = r0 + 8;
        float bi0 = b2[r0], bi1 = b2[r1];
        const float* res0 = x + (size_t)((1*BB+b)*CC + r0)*HW;
        const float* res1 = x + (size_t)((1*BB+b)*CC + r1)*HW;
        #pragma unroll
        for(int ni = 0; ni < 4; ni++){
            int nc = n0 + warp_n*32 + ni*8 + tg*2;
            float2 a0 = *(const float2*)&res0[nc];
            float2 a1 = *(const float2*)&res1[nc];
            float2 o0, o1;
            o0.x = acc[mi][ni][0] + bi0 + a0.x; o0.y = acc[mi][ni][1] + bi0 + a0.y;
            o1.x = acc[mi][ni][2] + bi1 + a1.x; o1.y = acc[mi][ni][3] + bi1 + a1.y;
            *(float2*)&out[(size_t)(b*CC+r0)*HW + nc] = o0;
            *(float2*)&out[(size_t)(b*CC+r1)*HW + nc] = o1;
        }
    }
}

// ---------------- launcher ---------------------------------------------------
extern "C" void kernel_launch(void* const* d_in, const int* in_sizes, int n_in,
                              void* d_out, int out_size)
{
    (void)in_sizes; (void)n_in; (void)out_size;
    const float* x   = (const float*)d_in[0];
    const float* Wq  = (const float*)d_in[1];
    const float* bq  = (const float*)d_in[2];
    const float* bnq = (const float*)d_in[3];
    const float* Wk_ = (const float*)d_in[4];
    const float* bk_ = (const float*)d_in[5];
    const float* bnk = (const float*)d_in[6];
    const float* Wv  = (const float*)d_in[7];
    const float* bv  = (const float*)d_in[8];
    const float* bnv = (const float*)d_in[9];
    const float* iw1 = (const float*)d_in[10];
    const float* ib1 = (const float*)d_in[11];
    const float* iw2 = (const float*)d_in[12];
    const float* ib2 = (const float*)d_in[13];
    const float* aiw = (const float*)d_in[14];
    const float* aib = (const float*)d_in[15];
    const float* aow = (const float*)d_in[16];
    const float* aob = (const float*)d_in[17];
    const float* cw  = (const float*)d_in[18];
    const float* cb1 = (const float*)d_in[19];
    const float* cbn = (const float*)d_in[20];
    const float* w2  = (const float*)d_in[21];
    const float* b2  = (const float*)d_in[22];
    float* out = (float*)d_out;

    k_pool<<<SS*BB*CC, 256>>>(x);
    k_imp<<<1, 256>>>(iw1, ib1, iw2, ib2);
    k_projT<<<dim3(32,2,36), 256>>>(x, Wq,bq,bnq, Wk_,bk_,bnk, Wv,bv,bnv);
    k_attninT<<<dim3(32,2,36), 256>>>(aiw, aib);
    k_attn<<<dim3(64,8), 256>>>();
    k_outT<<<dim3(32,2,4), 256>>>(aow, aob);
    k_convT<<<dim3(32,2,4), 256>>>(cw, cb1, cbn);
    k_finalT<<<dim3(32,2,4), 256>>>(w2, b2, x, out);
}

// round 6
// speedup vs baseline: 1.6730x; 1.0712x over previous
#include <cuda_runtime.h>
#include <cuda_bf16.h>
#include <cstdint>
#include <math.h>

#define SS 3
#define BB 4
#define CC 256
#define HW 4096
#define EPSf 1e-5f

// ---------------- scratch ----------------------------------------------------
__device__ float g_pooled[BB*SS*CC];
__device__ float g_wmix[BB*SS];
__device__ __nv_bfloat16 g_q [SS*BB*CC*HW];
__device__ __nv_bfloat16 g_k [SS*BB*CC*HW];
__device__ __nv_bfloat16 g_v [SS*BB*CC*HW];
__device__ __nv_bfloat16 g_qt[SS*BB*CC*HW];
__device__ __nv_bfloat16 g_kt[SS*BB*CC*HW];
__device__ __nv_bfloat16 g_vt[SS*BB*CC*HW];
__device__ __nv_bfloat16 g_o [SS*BB*CC*HW];
__device__ __nv_bfloat16 g_integr[BB*CC*HW];
__device__ __nv_bfloat16 g_y2[BB*CC*HW];

__device__ __forceinline__ float gelu_f(float x){
    return 0.5f * x * (1.0f + erff(x * 0.70710678118654752f));
}
__device__ __forceinline__ uint32_t pkbf(float lo, float hi){
    __nv_bfloat162 h = __float22bfloat162_rn(make_float2(lo, hi));
    return *(uint32_t*)&h;
}
__device__ __forceinline__ __nv_bfloat162 pk2(float lo, float hi){
    return __float22bfloat162_rn(make_float2(lo, hi));
}
__device__ __forceinline__ void mma16(float c[4], const uint32_t a[4], const uint32_t b[2]){
    asm volatile(
        "mma.sync.aligned.m16n8k16.row.col.f32.bf16.bf16.f32 "
        "{%0,%1,%2,%3}, {%4,%5,%6,%7}, {%8,%9}, {%0,%1,%2,%3};"
        : "+f"(c[0]), "+f"(c[1]), "+f"(c[2]), "+f"(c[3])
        : "r"(a[0]), "r"(a[1]), "r"(a[2]), "r"(a[3]), "r"(b[0]), "r"(b[1]));
}

// ---------------- GEMM building blocks ---------------------------------------
// CTA tile 128(M) x 256(N), BK=32 (16 bf16x2 pairs), 256 threads = 8 warps
// (2M x 4N), warp tile 64x64.
// SMEM: As[16][128] u32, pair kp: As[kp][(m+8kp)&127] = {A[m][2kp],A[m][2kp+1]}
//       Bs[16][256] u32, Bs[kp][(n+8kp)&255] = {X[2kp][n], X[2kp+1][n]}
// Fragment loads conflict-free (bank = g + 8*tg).

__device__ __forceinline__ void fetchA_pk(uint32_t rp[8], const float* Wt, int lda, int tid){
    int m = tid >> 1, kh = (tid & 1) * 16;
    const float4* s = (const float4*)(Wt + (size_t)m*lda + kh);
    float4 v0=s[0], v1=s[1], v2=s[2], v3=s[3];
    rp[0]=pkbf(v0.x,v0.y); rp[1]=pkbf(v0.z,v0.w);
    rp[2]=pkbf(v1.x,v1.y); rp[3]=pkbf(v1.z,v1.w);
    rp[4]=pkbf(v2.x,v2.y); rp[5]=pkbf(v2.z,v2.w);
    rp[6]=pkbf(v3.x,v3.y); rp[7]=pkbf(v3.z,v3.w);
}
__device__ __forceinline__ void storeA_pk(uint32_t* As, const uint32_t rp[8], int tid){
    int m = tid >> 1, kb = (tid & 1) * 8;
    #pragma unroll
    for(int i = 0; i < 8; i++){
        int kp = kb + i;
        As[kp*128 + ((m + 8*kp) & 127)] = rp[i];
    }
}
// B from fp32 source (16 n-cols per thread, rows 2kp & 2kp+1)
__device__ __forceinline__ void fetchB_f32(uint32_t rp[16], const float* Xt, int stride, int tid){
    int kp = tid >> 4, nb = (tid & 15) * 16;
    const float4* s0 = (const float4*)(Xt + (size_t)(2*kp)*stride + nb);
    const float4* s1 = (const float4*)(Xt + (size_t)(2*kp+1)*stride + nb);
    float a[16], b[16];
    #pragma unroll
    for(int i = 0; i < 4; i++){
        float4 va = s0[i], vb = s1[i];
        a[i*4+0]=va.x; a[i*4+1]=va.y; a[i*4+2]=va.z; a[i*4+3]=va.w;
        b[i*4+0]=vb.x; b[i*4+1]=vb.y; b[i*4+2]=vb.z; b[i*4+3]=vb.w;
    }
    #pragma unroll
    for(int j = 0; j < 16; j++) rp[j] = pkbf(a[j], b[j]);
}
// B from bf16 source
__device__ __forceinline__ void fetchB_bf(uint32_t rp[16], const __nv_bfloat16* Xt, int stride, int tid){
    int kp = tid >> 4, nb = (tid & 15) * 16;
    const uint4* s0 = (const uint4*)(Xt + (size_t)(2*kp)*stride + nb);
    const uint4* s1 = (const uint4*)(Xt + (size_t)(2*kp+1)*stride + nb);
    uint4 a0 = s0[0], a1 = s0[1];
    uint4 b0 = s1[0], b1 = s1[1];
    uint32_t A[8] = {a0.x,a0.y,a0.z,a0.w, a1.x,a1.y,a1.z,a1.w};
    uint32_t Bv[8]= {b0.x,b0.y,b0.z,b0.w, b1.x,b1.y,b1.z,b1.w};
    #pragma unroll
    for(int i = 0; i < 8; i++){
        rp[2*i]   = __byte_perm(A[i], Bv[i], 0x5410);
        rp[2*i+1] = __byte_perm(A[i], Bv[i], 0x7632);
    }
}
// B from bf16 source with fp32 scale
__device__ __forceinline__ void fetchB_bf_scl(uint32_t rp[16], const __nv_bfloat16* Xt, int stride, int tid, float scl){
    int kp = tid >> 4, nb = (tid & 15) * 16;
    const uint4* s0 = (const uint4*)(Xt + (size_t)(2*kp)*stride + nb);
    const uint4* s1 = (const uint4*)(Xt + (size_t)(2*kp+1)*stride + nb);
    uint4 a0 = s0[0], a1 = s0[1];
    uint4 b0 = s1[0], b1 = s1[1];
    uint32_t A[8] = {a0.x,a0.y,a0.z,a0.w, a1.x,a1.y,a1.z,a1.w};
    uint32_t Bv[8]= {b0.x,b0.y,b0.z,b0.w, b1.x,b1.y,b1.z,b1.w};
    #pragma unroll
    for(int i = 0; i < 8; i++){
        float2 fa = __bfloat1622float2(*(__nv_bfloat162*)&A[i]);
        float2 fb = __bfloat1622float2(*(__nv_bfloat162*)&Bv[i]);
        rp[2*i]   = pkbf(fa.x*scl, fb.x*scl);
        rp[2*i+1] = pkbf(fa.y*scl, fb.y*scl);
    }
}
__device__ __forceinline__ void storeB_pk(uint32_t* Bs, const uint32_t rp[16], int tid){
    int kp = tid >> 4, nb = (tid & 15) * 16;
    #pragma unroll
    for(int j = 0; j < 16; j++){
        Bs[kp*256 + ((nb + j + 8*kp) & 255)] = rp[j];
    }
}

__device__ __forceinline__ void mma_compute64(const uint32_t* As, const uint32_t* Bs,
                                              float acc[4][8][4], int warp_m, int warp_n, int lane){
    int g = lane >> 2, tg = lane & 3;
    #pragma unroll
    for(int ks = 0; ks < 2; ks++){
        int kp1 = ks*8 + tg, kp2 = kp1 + 4;
        uint32_t a[4][4], bf[8][2];
        #pragma unroll
        for(int mi = 0; mi < 4; mi++){
            int m = warp_m*64 + mi*16 + g;
            a[mi][0] = As[kp1*128 + ((m     + 8*kp1) & 127)];
            a[mi][1] = As[kp1*128 + ((m + 8 + 8*kp1) & 127)];
            a[mi][2] = As[kp2*128 + ((m     + 8*kp2) & 127)];
            a[mi][3] = As[kp2*128 + ((m + 8 + 8*kp2) & 127)];
        }
        #pragma unroll
        for(int ni = 0; ni < 8; ni++){
            int n = warp_n*64 + ni*8 + g;
            bf[ni][0] = Bs[kp1*256 + ((n + 8*kp1) & 255)];
            bf[ni][1] = Bs[kp2*256 + ((n + 8*kp2) & 255)];
        }
        #pragma unroll
        for(int mi = 0; mi < 4; mi++)
            #pragma unroll
            for(int ni = 0; ni < 8; ni++)
                mma16(acc[mi][ni], a[mi], bf[ni]);
    }
}

#define GEMM_PRE() \
    __shared__ uint32_t Asb[2][16*128]; \
    __shared__ uint32_t Bsb[2][16*256]; \
    float acc[4][8][4]; \
    _Pragma("unroll") \
    for(int i=0;i<4;i++) _Pragma("unroll") for(int j=0;j<8;j++) _Pragma("unroll") for(int r=0;r<4;r++) acc[i][j][r]=0.f; \
    int tid = threadIdx.x; \
    int wid = tid >> 5, lane = tid & 31; \
    int warp_m = wid >> 2, warp_n = wid & 3; \
    int g = lane >> 2, tg = lane & 3; (void)g; (void)tg;

// ---------------- stage 1: spatial mean pool --------------------------------
__global__ void k_pool(const float* __restrict__ x){
    int id = blockIdx.x;
    int c = id & 255;
    int b = (id >> 8) & 3;
    int s = id >> 10;
    const float* p = x + (size_t)((s*BB+b)*CC + c) * HW;
    float sum = 0.f;
    for(int i = threadIdx.x; i < HW; i += 256) sum += p[i];
    __shared__ float red[8];
    #pragma unroll
    for(int o = 16; o > 0; o >>= 1) sum += __shfl_down_sync(0xffffffffu, sum, o);
    if((threadIdx.x & 31) == 0) red[threadIdx.x >> 5] = sum;
    __syncthreads();
    if(threadIdx.x == 0){
        float t = 0.f;
        #pragma unroll
        for(int i = 0; i < 8; i++) t += red[i];
        g_pooled[(b*SS + s)*CC + c] = t * (1.0f / HW);
    }
}

// ---------------- stage 2: importance MLP + softmax --------------------------
__global__ void k_imp(const float* __restrict__ iw1, const float* __restrict__ ib1,
                      const float* __restrict__ iw2, const float* __restrict__ ib2){
    __shared__ float h[BB][CC];
    __shared__ float lg[BB][SS];
    int t = threadIdx.x;
    for(int b = 0; b < BB; b++){
        float acc = ib1[t];
        const float4* pw = (const float4*)(iw1 + t * (SS*CC));
        const float4* pp = (const float4*)(g_pooled + b * (SS*CC));
        #pragma unroll 4
        for(int i = 0; i < (SS*CC)/4; i++){
            float4 a = pw[i], c = pp[i];
            acc += a.x*c.x + a.y*c.y + a.z*c.z + a.w*c.w;
        }
        h[b][t] = gelu_f(acc);
    }
    __syncthreads();
    if(t < BB*SS){
        int b = t / SS, s = t % SS;
        float acc = ib2[s];
        for(int c = 0; c < CC; c++) acc += h[b][c] * iw2[s*CC + c];
        lg[b][s] = acc;
    }
    __syncthreads();
    if(t < BB){
        float m  = fmaxf(lg[t][0], fmaxf(lg[t][1], lg[t][2]));
        float e0 = expf(lg[t][0]-m), e1 = expf(lg[t][1]-m), e2 = expf(lg[t][2]-m);
        float inv = 1.0f / (e0 + e1 + e2);
        g_wmix[t*SS+0] = e0*inv; g_wmix[t*SS+1] = e1*inv; g_wmix[t*SS+2] = e2*inv;
    }
}

// ---------------- stage 3: q/k/v projection ----------------------------------
__global__ __launch_bounds__(256,1) void k_projT(
    const float* __restrict__ x,
    const float* __restrict__ Wq, const float* __restrict__ bq, const float* __restrict__ bnq,
    const float* __restrict__ Wk_, const float* __restrict__ bk_, const float* __restrict__ bnk,
    const float* __restrict__ Wv, const float* __restrict__ bv, const float* __restrict__ bnv)
{
    int z = blockIdx.z;
    int which = z / 12;
    int s = (z % 12) >> 2;
    int b = z & 3;
    const float *W, *bias, *bn; __nv_bfloat16* out;
    if(which == 0){ W = Wq;  bias = bq;  bn = bnq; out = g_q; }
    else if(which == 1){ W = Wk_; bias = bk_; bn = bnk; out = g_k; }
    else { W = Wv; bias = bv; bn = bnv; out = g_v; }
    W += s * CC * CC;
    const float* X = x + (size_t)(s*BB+b)*CC*HW;
    __nv_bfloat16* O = out + (size_t)(s*BB+b)*CC*HW;
    int m0 = blockIdx.y * 128;
    int n0 = blockIdx.x * 256;

    GEMM_PRE();
    uint32_t ra[8], rb[16];
    fetchA_pk(ra, W + (size_t)m0*CC, CC, tid);
    fetchB_f32(rb, X + n0, HW, tid);
    storeA_pk(Asb[0], ra, tid);
    storeB_pk(Bsb[0], rb, tid);
    __syncthreads();
    const int nk = CC/32;
    int cur = 0;
    for(int it = 0; it < nk; it++){
        bool more = (it+1 < nk);
        if(more){
            fetchA_pk(ra, W + (size_t)m0*CC + (it+1)*32, CC, tid);
            fetchB_f32(rb, X + (size_t)(it+1)*32*HW + n0, HW, tid);
        }
        mma_compute64(Asb[cur], Bsb[cur], acc, warp_m, warp_n, lane);
        if(more){
            storeA_pk(Asb[cur^1], ra, tid);
            storeB_pk(Bsb[cur^1], rb, tid);
        }
        __syncthreads();
        cur ^= 1;
    }
    #pragma unroll
    for(int mi = 0; mi < 4; mi++){
        int r0 = m0 + warp_m*64 + mi*16 + g;
        int r1 = r0 + 8;
        float sc0 = bn[(s*4+0)*CC+r0] * rsqrtf(bn[(s*4+3)*CC+r0] + EPSf);
        float sc1 = bn[(s*4+0)*CC+r1] * rsqrtf(bn[(s*4+3)*CC+r1] + EPSf);
        float be0 = bn[(s*4+1)*CC+r0], be1 = bn[(s*4+1)*CC+r1];
        float mu0 = bn[(s*4+2)*CC+r0], mu1 = bn[(s*4+2)*CC+r1];
        float bi0 = bias[s*CC+r0], bi1 = bias[s*CC+r1];
        #pragma unroll
        for(int ni = 0; ni < 8; ni++){
            int nc = n0 + warp_n*64 + ni*8 + tg*2;
            *(__nv_bfloat162*)&O[(size_t)r0*HW + nc] =
                pk2(gelu_f((acc[mi][ni][0] + bi0 - mu0)*sc0 + be0),
                    gelu_f((acc[mi][ni][1] + bi0 - mu0)*sc0 + be0));
            *(__nv_bfloat162*)&O[(size_t)r1*HW + nc] =
                pk2(gelu_f((acc[mi][ni][2] + bi1 - mu1)*sc1 + be1),
                    gelu_f((acc[mi][ni][3] + bi1 - mu1)*sc1 + be1));
        }
    }
}

// ---------------- stage 4: attn_in projection --------------------------------
__global__ __launch_bounds__(256,1) void k_attninT(const float* __restrict__ aiw,
                                                   const float* __restrict__ aib)
{
    int z = blockIdx.z;
    int which = z / 12;
    int s = (z % 12) >> 2;
    int b = z & 3;
    const float* W = aiw + which * CC * CC;
    const float* bias = aib + which * CC;
    const __nv_bfloat16* Xg; __nv_bfloat16* Og;
    if(which == 0){ Xg = g_q; Og = g_qt; }
    else if(which == 1){ Xg = g_k; Og = g_kt; }
    else { Xg = g_v; Og = g_vt; }
    const __nv_bfloat16* X = Xg + (size_t)(s*BB+b)*CC*HW;
    __nv_bfloat16*       O = Og + (size_t)(s*BB+b)*CC*HW;
    int m0 = blockIdx.y * 128;
    int n0 = blockIdx.x * 256;

    GEMM_PRE();
    uint32_t ra[8], rb[16];
    fetchA_pk(ra, W + (size_t)m0*CC, CC, tid);
    fetchB_bf(rb, X + n0, HW, tid);
    storeA_pk(Asb[0], ra, tid);
    storeB_pk(Bsb[0], rb, tid);
    __syncthreads();
    const int nk = CC/32;
    int cur = 0;
    for(int it = 0; it < nk; it++){
        bool more = (it+1 < nk);
        if(more){
            fetchA_pk(ra, W + (size_t)m0*CC + (it+1)*32, CC, tid);
            fetchB_bf(rb, X + (size_t)(it+1)*32*HW + n0, HW, tid);
        }
        mma_compute64(Asb[cur], Bsb[cur], acc, warp_m, warp_n, lane);
        if(more){
            storeA_pk(Asb[cur^1], ra, tid);
            storeB_pk(Bsb[cur^1], rb, tid);
        }
        __syncthreads();
        cur ^= 1;
    }
    #pragma unroll
    for(int mi = 0; mi < 4; mi++){
        int r0 = m0 + warp_m*64 + mi*16 + g;
        int r1 = r0 + 8;
        float bi0 = bias[r0], bi1 = bias[r1];
        #pragma unroll
        for(int ni = 0; ni < 8; ni++){
            int nc = n0 + warp_n*64 + ni*8 + tg*2;
            *(__nv_bfloat162*)&O[(size_t)r0*HW + nc] =
                pk2(acc[mi][ni][0] + bi0, acc[mi][ni][1] + bi0);
            *(__nv_bfloat162*)&O[(size_t)r1*HW + nc] =
                pk2(acc[mi][ni][2] + bi1, acc[mi][ni][3] + bi1);
        }
    }
}

// ---------------- stage 5: tiny attention over S=3 ---------------------------
__global__ void k_attn(){
    int n = blockIdx.x * blockDim.x + threadIdx.x;
    int head = blockIdx.y;
    int b = n >> 12, p = n & 4095;
    int off0 = ((0*BB+b)*CC)*HW + p;
    int off1 = ((1*BB+b)*CC)*HW + p;
    int off2 = ((2*BB+b)*CC)*HW + p;
    int cbase = head * 32;

    float sc[3][3];
    #pragma unroll
    for(int i=0;i<3;i++){
        #pragma unroll
        for(int j=0;j<3;j++) sc[i][j]=0.f; }

    #pragma unroll 8
    for(int d = 0; d < 32; d++){
        int co = (cbase + d) * HW;
        float q0=__bfloat162float(g_qt[off0+co]), q1=__bfloat162float(g_qt[off1+co]), q2=__bfloat162float(g_qt[off2+co]);
        float k0=__bfloat162float(g_kt[off0+co]), k1=__bfloat162float(g_kt[off1+co]), k2=__bfloat162float(g_kt[off2+co]);
        sc[0][0]+=q0*k0; sc[0][1]+=q0*k1; sc[0][2]+=q0*k2;
        sc[1][0]+=q1*k0; sc[1][1]+=q1*k1; sc[1][2]+=q1*k2;
        sc[2][0]+=q2*k0; sc[2][1]+=q2*k1; sc[2][2]+=q2*k2;
    }
    const float scale = 0.17677669529663688f;
    float at[3][3];
    #pragma unroll
    for(int s_ = 0; s_ < 3; s_++){
        float a0 = sc[s_][0]*scale, a1 = sc[s_][1]*scale, a2 = sc[s_][2]*scale;
        float m = fmaxf(a0, fmaxf(a1, a2));
        float e0 = expf(a0-m), e1 = expf(a1-m), e2 = expf(a2-m);
        float inv = 1.0f / (e0+e1+e2);
        at[s_][0]=e0*inv; at[s_][1]=e1*inv; at[s_][2]=e2*inv;
    }
    #pragma unroll 8
    for(int d = 0; d < 32; d++){
        int co = (cbase + d) * HW;
        float v0=__bfloat162float(g_vt[off0+co]), v1=__bfloat162float(g_vt[off1+co]), v2=__bfloat162float(g_vt[off2+co]);
        g_o[off0+co] = __float2bfloat16(at[0][0]*v0 + at[0][1]*v1 + at[0][2]*v2);
        g_o[off1+co] = __float2bfloat16(at[1][0]*v0 + at[1][1]*v1 + at[1][2]*v2);
        g_o[off2+co] = __float2bfloat16(at[2][0]*v0 + at[2][1]*v1 + at[2][2]*v2);
    }
}

// ---------------- stage 6: attn_out + weighted s-combine (K=768) -------------
__global__ __launch_bounds__(256,1) void k_outT(const float* __restrict__ Wo,
                                                const float* __restrict__ bo)
{
    int b = blockIdx.z;
    int m0 = blockIdx.y * 128;
    int n0 = blockIdx.x * 256;
    float wmix[3] = { g_wmix[b*3+0], g_wmix[b*3+1], g_wmix[b*3+2] };

    GEMM_PRE();
    uint32_t ra[8], rb[16];
    fetchA_pk(ra, Wo + (size_t)m0*CC, CC, tid);
    fetchB_bf_scl(rb, g_o + (size_t)(b*CC)*HW + n0, HW, tid, wmix[0]);
    storeA_pk(Asb[0], ra, tid);
    storeB_pk(Bsb[0], rb, tid);
    __syncthreads();
    const int nk = (SS*CC)/32;
    int cur = 0;
    for(int it = 0; it < nk; it++){
        bool more = (it+1 < nk);
        if(more){
            int k0 = (it+1)*32;
            int s  = k0 >> 8;
            int cb2 = k0 & 255;
            fetchA_pk(ra, Wo + (size_t)m0*CC + cb2, CC, tid);
            fetchB_bf_scl(rb, g_o + (size_t)((s*BB+b)*CC + cb2)*HW + n0, HW, tid, wmix[s]);
        }
        mma_compute64(Asb[cur], Bsb[cur], acc, warp_m, warp_n, lane);
        if(more){
            storeA_pk(Asb[cur^1], ra, tid);
            storeB_pk(Bsb[cur^1], rb, tid);
        }
        __syncthreads();
        cur ^= 1;
    }
    #pragma unroll
    for(int mi = 0; mi < 4; mi++){
        int r0 = m0 + warp_m*64 + mi*16 + g;
        int r1 = r0 + 8;
        float bi0 = bo[r0], bi1 = bo[r1];
        #pragma unroll
        for(int ni = 0; ni < 8; ni++){
            int nc = n0 + warp_n*64 + ni*8 + tg*2;
            *(__nv_bfloat162*)&g_integr[(size_t)(b*CC+r0)*HW + nc] =
                pk2(acc[mi][ni][0] + bi0, acc[mi][ni][1] + bi0);
            *(__nv_bfloat162*)&g_integr[(size_t)(b*CC+r1)*HW + nc] =
                pk2(acc[mi][ni][2] + bi1, acc[mi][ni][3] + bi1);
        }
    }
}

// ---------------- stage 7: 3x3 conv as GEMM (K=2304) -------------------------
__device__ __forceinline__ void fetchB_conv(uint32_t rp[16], int b, int k0, int n0, int tid){
    int kp = tid >> 4, nb = (tid & 15) * 16;
    unsigned short v[2][16];
    #pragma unroll
    for(int half = 0; half < 2; half++){
        int kkg = k0 + 2*kp + half;
        int c  = kkg / 9;
        int r9 = kkg - c*9;
        int kh = r9 / 3, kw = r9 - kh*3;
        const unsigned short* src = (const unsigned short*)(g_integr + (size_t)(b*CC + c)*HW);
        #pragma unroll
        for(int j = 0; j < 16; j++){
            int pix = n0 + nb + j;
            int hh = (pix >> 6) + kh - 1;
            int ww = (pix & 63) + kw - 1;
            unsigned short val = 0;
            if((unsigned)hh < 64u && (unsigned)ww < 64u) val = src[hh*64 + ww];
            v[half][j] = val;
        }
    }
    #pragma unroll
    for(int j = 0; j < 16; j++)
        rp[j] = (uint32_t)v[0][j] | ((uint32_t)v[1][j] << 16);
}

__global__ __launch_bounds__(256,1) void k_convT(const float* __restrict__ Wc,
                                                 const float* __restrict__ b1,
                                                 const float* __restrict__ opbn)
{
    int b = blockIdx.z;
    int m0 = blockIdx.y * 128;
    int n0 = blockIdx.x * 256;

    GEMM_PRE();
    uint32_t ra[8], rb[16];
    fetchA_pk(ra, Wc + (size_t)m0*(CC*9), CC*9, tid);
    fetchB_conv(rb, b, 0, n0, tid);
    storeA_pk(Asb[0], ra, tid);
    storeB_pk(Bsb[0], rb, tid);
    __syncthreads();
    const int nk = (CC*9)/32;
    int cur = 0;
    for(int it = 0; it < nk; it++){
        bool more = (it+1 < nk);
        if(more){
            fetchA_pk(ra, Wc + (size_t)m0*(CC*9) + (it+1)*32, CC*9, tid);
            fetchB_conv(rb, b, (it+1)*32, n0, tid);
        }
        mma_compute64(Asb[cur], Bsb[cur], acc, warp_m, warp_n, lane);
        if(more){
            storeA_pk(Asb[cur^1], ra, tid);
            storeB_pk(Bsb[cur^1], rb, tid);
        }
        __syncthreads();
        cur ^= 1;
    }
    #pragma unroll
    for(int mi = 0; mi < 4; mi++){
        int r0 = m0 + warp_m*64 + mi*16 + g;
        int r1 = r0 + 8;
        float sc0 = opbn[0*CC+r0] * rsqrtf(opbn[3*CC+r0] + EPSf);
        float sc1 = opbn[0*CC+r1] * rsqrtf(opbn[3*CC+r1] + EPSf);
        float be0 = opbn[1*CC+r0], be1 = opbn[1*CC+r1];
        float mu0 = opbn[2*CC+r0], mu1 = opbn[2*CC+r1];
        float bi0 = b1[r0], bi1 = b1[r1];
        #pragma unroll
        for(int ni = 0; ni < 8; ni++){
            int nc = n0 + warp_n*64 + ni*8 + tg*2;
            *(__nv_bfloat162*)&g_y2[(size_t)(b*CC+r0)*HW + nc] =
                pk2(gelu_f((acc[mi][ni][0] + bi0 - mu0)*sc0 + be0),
                    gelu_f((acc[mi][ni][1] + bi0 - mu0)*sc0 + be0));
            *(__nv_bfloat162*)&g_y2[(size_t)(b*CC+r1)*HW + nc] =
                pk2(gelu_f((acc[mi][ni][2] + bi1 - mu1)*sc1 + be1),
                    gelu_f((acc[mi][ni][3] + bi1 - mu1)*sc1 + be1));
        }
    }
}

// ---------------- stage 8: final 1x1 + residual ------------------------------
__global__ __launch_bounds__(256,1) void k_finalT(const float* __restrict__ W2,
                                                  const float* __restrict__ b2,
                                                  const float* __restrict__ x,
                                                  float* __restrict__ out)
{
    int b = blockIdx.z;
    int m0 = blockIdx.y * 128;
    int n0 = blockIdx.x * 256;

    GEMM_PRE();
    uint32_t ra[8], rb[16];
    fetchA_pk(ra, W2 + (size_t)m0*CC, CC, tid);
    fetchB_bf(rb, g_y2 + (size_t)(b*CC)*HW + n0, HW, tid);
    storeA_pk(Asb[0], ra, tid);
    storeB_pk(Bsb[0], rb, tid);
    __syncthreads();
    const int nk = CC/32;
    int cur = 0;
    for(int it = 0; it < nk; it++){
        bool more = (it+1 < nk);
        if(more){
            fetchA_pk(ra, W2 + (size_t)m0*CC + (it+1)*32, CC, tid);
            fetchB_bf(rb, g_y2 + (size_t)(b*CC + (it+1)*32)*HW + n0, HW, tid);
        }
        mma_compute64(Asb[cur], Bsb[cur], acc, warp_m, warp_n, lane);
        if(more){
            storeA_pk(Asb[cur^1], ra, tid);
            storeB_pk(Bsb[cur^1], rb, tid);
        }
        __syncthreads();
        cur ^= 1;
    }
    #pragma unroll
    for(int mi = 0; mi < 4; mi++){
        int r0 = m0 + warp_m*64 + mi*16 + g;
        int r1 = r0 + 8;
        float bi0 = b2[r0], bi1 = b2[r1];
        const float* res0 = x + (size_t)((1*BB+b)*CC + r0)*HW;
        const float* res1 = x + (size_t)((1*BB+b)*CC + r1)*HW;
        #pragma unroll
        for(int ni = 0; ni < 8; ni++){
            int nc = n0 + warp_n*64 + ni*8 + tg*2;
            float2 a0 = *(const float2*)&res0[nc];
            float2 a1 = *(const float2*)&res1[nc];
            float2 o0, o1;
            o0.x = acc[mi][ni][0] + bi0 + a0.x; o0.y = acc[mi][ni][1] + bi0 + a0.y;
            o1.x = acc[mi][ni][2] + bi1 + a1.x; o1.y = acc[mi][ni][3] + bi1 + a1.y;
            *(float2*)&out[(size_t)(b*CC+r0)*HW + nc] = o0;
            *(float2*)&out[(size_t)(b*CC+r1)*HW + nc] = o1;
        }
    }
}

// ---------------- launcher ---------------------------------------------------
extern "C" void kernel_launch(void* const* d_in, const int* in_sizes, int n_in,
                              void* d_out, int out_size)
{
    (void)in_sizes; (void)n_in; (void)out_size;
    const float* x   = (const float*)d_in[0];
    const float* Wq  = (const float*)d_in[1];
    const float* bq  = (const float*)d_in[2];
    const float* bnq = (const float*)d_in[3];
    const float* Wk_ = (const float*)d_in[4];
    const float* bk_ = (const float*)d_in[5];
    const float* bnk = (const float*)d_in[6];
    const float* Wv  = (const float*)d_in[7];
    const float* bv  = (const float*)d_in[8];
    const float* bnv = (const float*)d_in[9];
    const float* iw1 = (const float*)d_in[10];
    const float* ib1 = (const float*)d_in[11];
    const float* iw2 = (const float*)d_in[12];
    const float* ib2 = (const float*)d_in[13];
    const float* aiw = (const float*)d_in[14];
    const float* aib = (const float*)d_in[15];
    const float* aow = (const float*)d_in[16];
    const float* aob = (const float*)d_in[17];
    const float* cw  = (const float*)d_in[18];
    const float* cb1 = (const float*)d_in[19];
    const float* cbn = (const float*)d_in[20];
    const float* w2  = (const float*)d_in[21];
    const float* b2  = (const float*)d_in[22];
    float* out = (float*)d_out;

    k_pool<<<SS*BB*CC, 256>>>(x);
    k_imp<<<1, 256>>>(iw1, ib1, iw2, ib2);
    k_projT<<<dim3(16,2,36), 256>>>(x, Wq,bq,bnq, Wk_,bk_,bnk, Wv,bv,bnv);
    k_attninT<<<dim3(16,2,36), 256>>>(aiw, aib);
    k_attn<<<dim3(64,8), 256>>>();
    k_outT<<<dim3(16,2,4), 256>>>(aow, aob);
    k_convT<<<dim3(16,2,4), 256>>>(cw, cb1, cbn);
    k_finalT<<<dim3(16,2,4), 256>>>(w2, b2, x, out);
}

// round 7
// speedup vs baseline: 2.5507x; 1.5247x over previous
#include <cuda_runtime.h>
#include <cuda_bf16.h>
#include <cstdint>
#include <math.h>

#define SS 3
#define BB 4
#define CC 256
#define HW 4096
#define EPSf 1e-5f

// ---------------- scratch ----------------------------------------------------
__device__ float g_pooled[BB*SS*CC];
__device__ float g_wmix[BB*SS];
__device__ __align__(256) __nv_bfloat16 g_x_bf[SS*BB*CC*HW];
__device__ __align__(256) __nv_bfloat16 g_q [SS*BB*CC*HW];
__device__ __align__(256) __nv_bfloat16 g_k [SS*BB*CC*HW];
__device__ __align__(256) __nv_bfloat16 g_v [SS*BB*CC*HW];
__device__ __align__(256) __nv_bfloat16 g_qt[SS*BB*CC*HW];
__device__ __align__(256) __nv_bfloat16 g_kt[SS*BB*CC*HW];
__device__ __align__(256) __nv_bfloat16 g_vt[SS*BB*CC*HW];
__device__ __align__(256) __nv_bfloat16 g_o [SS*BB*CC*HW];
__device__ __align__(256) __nv_bfloat16 g_integr[BB*CC*HW];
__device__ __align__(256) __nv_bfloat16 g_y2[BB*CC*HW];
// bf16 weights
__device__ __align__(256) __nv_bfloat16 g_wq_bf [SS*CC*CC];
__device__ __align__(256) __nv_bfloat16 g_wk_bf [SS*CC*CC];
__device__ __align__(256) __nv_bfloat16 g_wv_bf [SS*CC*CC];
__device__ __align__(256) __nv_bfloat16 g_aiw_bf[3*CC*CC];
__device__ __align__(256) __nv_bfloat16 g_aow_bf[CC*CC];
__device__ __align__(256) __nv_bfloat16 g_cw_bf [CC*CC*9];
__device__ __align__(256) __nv_bfloat16 g_w2_bf [CC*CC];

__device__ __forceinline__ float gelu_f(float x){
    return 0.5f * x * (1.0f + erff(x * 0.70710678118654752f));
}
__device__ __forceinline__ uint32_t pkbf(float lo, float hi){
    __nv_bfloat162 h = __float22bfloat162_rn(make_float2(lo, hi));
    return *(uint32_t*)&h;
}
__device__ __forceinline__ __nv_bfloat162 pk2(float lo, float hi){
    return __float22bfloat162_rn(make_float2(lo, hi));
}
__device__ __forceinline__ void mma16(float c[4], const uint32_t a[4], const uint32_t b[2]){
    asm volatile(
        "mma.sync.aligned.m16n8k16.row.col.f32.bf16.bf16.f32 "
        "{%0,%1,%2,%3}, {%4,%5,%6,%7}, {%8,%9}, {%0,%1,%2,%3};"
        : "+f"(c[0]), "+f"(c[1]), "+f"(c[2]), "+f"(c[3])
        : "r"(a[0]), "r"(a[1]), "r"(a[2]), "r"(a[3]), "r"(b[0]), "r"(b[1]));
}

#define CP16(dst, src) asm volatile("cp.async.cg.shared.global [%0], [%1], 16;" :: "r"(dst), "l"(src))
#define CP_COMMIT()    asm volatile("cp.async.commit_group;" ::: "memory")
#define CP_WAIT1()     asm volatile("cp.async.wait_group 1;" ::: "memory")
#define CP_WAIT0()     asm volatile("cp.async.wait_group 0;" ::: "memory")
#define LDSM_X4(r, addr) \
    asm volatile("ldmatrix.sync.aligned.m8n8.x4.shared.b16 {%0,%1,%2,%3}, [%4];" \
        : "=r"((r)[0]), "=r"((r)[1]), "=r"((r)[2]), "=r"((r)[3]) : "r"(addr))
#define LDSM_X4T(r, addr) \
    asm volatile("ldmatrix.sync.aligned.m8n8.x4.trans.shared.b16 {%0,%1,%2,%3}, [%4];" \
        : "=r"((r)[0]), "=r"((r)[1]), "=r"((r)[2]), "=r"((r)[3]) : "r"(addr))

// ---------------- GEMM core ---------------------------------------------------
// CTA tile 128(M) x 128(N), BK=32 bf16, 256 thr = 8 warps (2M x 4N), warp 64x32.
// A smem (8KB/stage): row-pair packed, addr(m,u) = (m>>1)*128 + ((((m&1)<<2)|u)^((m>>1)&7))*16
//   (u = 16B unit within 64B row, 0..3)
// B smem (8KB/stage): rows k (256B), addr(k,u) = k*256 + ((u^(k&7))*16)  (u 0..15)
// Both layouts ldmatrix-phase conflict-free (derived in notes).

__device__ __forceinline__ void cpA(uint32_t As, const __nv_bfloat16* W, int lda, int tid){
    #pragma unroll
    for(int i = 0; i < 2; i++){
        int id = tid + i*256;
        int m = id >> 2, u = id & 3;
        const __nv_bfloat16* src = W + (size_t)m*lda + u*8;
        uint32_t unit8 = (uint32_t)((((m&1)<<2) | u) ^ ((m>>1)&7));
        CP16(As + ((m>>1)<<7) + (unit8<<4), src);
    }
}
__device__ __forceinline__ void cpB(uint32_t Bs, const __nv_bfloat16* X, size_t stride, int tid){
    #pragma unroll
    for(int i = 0; i < 2; i++){
        int id = tid + i*256;
        int k = id >> 4, u = id & 15;
        const __nv_bfloat16* src = X + (size_t)k*stride + u*8;
        CP16(Bs + (k<<8) + (((uint32_t)(u ^ (k&7)))<<4), src);
    }
}

__device__ __forceinline__ void chunk_mma(uint32_t As, uint32_t Bs, float acc[4][4][4],
                                          int warp_m, int warp_n, int lane){
    int ml = lane & 15, sel = lane >> 4;
    #pragma unroll
    for(int kb = 0; kb < 2; kb++){
        uint32_t a[4][4], bb[2][4];
        #pragma unroll
        for(int mt = 0; mt < 4; mt++){
            int m = warp_m*64 + mt*16 + ml;
            int unit = kb*2 + sel;
            uint32_t addr = As + ((m>>1)<<7) +
                ((uint32_t)(((((m&1)<<2) | unit) ^ ((m>>1)&7)))<<4);
            LDSM_X4(a[mt], addr);
        }
        #pragma unroll
        for(int np = 0; np < 2; np++){
            int kk = kb*16 + ml;
            int u = warp_n*4 + np*2 + sel;
            uint32_t addr = Bs + (kk<<8) + (((uint32_t)(u ^ (kk&7)))<<4);
            LDSM_X4T(bb[np], addr);
        }
        #pragma unroll
        for(int mt = 0; mt < 4; mt++)
            #pragma unroll
            for(int nt = 0; nt < 4; nt++)
                mma16(acc[mt][nt], a[mt], bb[nt>>1] + ((nt&1)<<1));
    }
}

#define GEMM_PRE() \
    __shared__ __align__(16) uint32_t smA[3][2048]; \
    __shared__ __align__(16) uint32_t smB[3][2048]; \
    uint32_t AsB = (uint32_t)__cvta_generic_to_shared(smA); \
    uint32_t BsB = (uint32_t)__cvta_generic_to_shared(smB); \
    float acc[4][4][4]; \
    _Pragma("unroll") \
    for(int i=0;i<4;i++) _Pragma("unroll") for(int j=0;j<4;j++) _Pragma("unroll") for(int r=0;r<4;r++) acc[i][j][r]=0.f; \
    int tid = threadIdx.x; \
    int wid = tid >> 5, lane = tid & 31; \
    int warp_m = wid >> 2, warp_n = wid & 3; \
    int g = lane >> 2, tg = lane & 3; (void)g; (void)tg;

// standard 3-stage mainloop over linear-strided B
#define GEMM_LOOP(NK, APTR, BPTR) \
    cpA(AsB,        APTR(0), lda, tid); cpB(BsB,        BPTR(0), strideB, tid); CP_COMMIT(); \
    cpA(AsB + 8192, APTR(1), lda, tid); cpB(BsB + 8192, BPTR(1), strideB, tid); CP_COMMIT(); \
    for(int it = 0; it < (NK); it++){ \
        if(it + 1 < (NK)) { CP_WAIT1(); } else { CP_WAIT0(); } \
        __syncthreads(); \
        if(it + 2 < (NK)){ \
            int st = (it+2)%3; \
            cpA(AsB + st*8192, APTR(it+2), lda, tid); \
            cpB(BsB + st*8192, BPTR(it+2), strideB, tid); \
            CP_COMMIT(); \
        } \
        int cb = it % 3; \
        chunk_mma(AsB + cb*8192, BsB + cb*8192, acc, warp_m, warp_n, lane); \
    }

// ---------------- prep: weight & input conversion -----------------------------
__global__ void k_cvtW(const float* Wq, const float* Wk_, const float* Wv,
                       const float* aiw, const float* aow, const float* cw, const float* w2){
    int i = (blockIdx.x*256 + threadIdx.x) * 4;
    const float* src; __nv_bfloat16* dst; int off;
    if(i < 196608){ src=Wq;  dst=g_wq_bf;  off=i; }
    else if(i <  393216){ src=Wk_; dst=g_wk_bf;  off=i-196608; }
    else if(i <  589824){ src=Wv;  dst=g_wv_bf;  off=i-393216; }
    else if(i <  786432){ src=aiw; dst=g_aiw_bf; off=i-589824; }
    else if(i <  851968){ src=aow; dst=g_aow_bf; off=i-786432; }
    else if(i < 1441792){ src=cw;  dst=g_cw_bf;  off=i-851968; }
    else if(i < 1507328){ src=w2;  dst=g_w2_bf;  off=i-1441792; }
    else return;
    float4 v = *(const float4*)(src + off);
    uint2 o; o.x = pkbf(v.x, v.y); o.y = pkbf(v.z, v.w);
    *(uint2*)(dst + off) = o;
}
__global__ void k_cvtX(const float* x){
    size_t i = (size_t)(blockIdx.x*256 + threadIdx.x) * 8;
    float4 a = *(const float4*)(x + i);
    float4 b = *(const float4*)(x + i + 4);
    uint4 o;
    o.x = pkbf(a.x,a.y); o.y = pkbf(a.z,a.w);
    o.z = pkbf(b.x,b.y); o.w = pkbf(b.z,b.w);
    *(uint4*)(g_x_bf + i) = o;
}

// ---------------- stage 1: spatial mean pool ----------------------------------
__global__ void k_pool(const float* __restrict__ x){
    int id = blockIdx.x;
    int c = id & 255;
    int b = (id >> 8) & 3;
    int s = id >> 10;
    const float* p = x + (size_t)((s*BB+b)*CC + c) * HW;
    float sum = 0.f;
    for(int i = threadIdx.x; i < HW; i += 256) sum += p[i];
    __shared__ float red[8];
    #pragma unroll
    for(int o = 16; o > 0; o >>= 1) sum += __shfl_down_sync(0xffffffffu, sum, o);
    if((threadIdx.x & 31) == 0) red[threadIdx.x >> 5] = sum;
    __syncthreads();
    if(threadIdx.x == 0){
        float t = 0.f;
        #pragma unroll
        for(int i = 0; i < 8; i++) t += red[i];
        g_pooled[(b*SS + s)*CC + c] = t * (1.0f / HW);
    }
}

// ---------------- stage 2: importance MLP + softmax ---------------------------
__global__ void k_imp(const float* __restrict__ iw1, const float* __restrict__ ib1,
                      const float* __restrict__ iw2, const float* __restrict__ ib2){
    __shared__ float h[BB][CC];
    __shared__ float lg[BB][SS];
    int t = threadIdx.x;
    for(int b = 0; b < BB; b++){
        float acc = ib1[t];
        const float4* pw = (const float4*)(iw1 + t * (SS*CC));
        const float4* pp = (const float4*)(g_pooled + b * (SS*CC));
        #pragma unroll 4
        for(int i = 0; i < (SS*CC)/4; i++){
            float4 a = pw[i], c = pp[i];
            acc += a.x*c.x + a.y*c.y + a.z*c.z + a.w*c.w;
        }
        h[b][t] = gelu_f(acc);
    }
    __syncthreads();
    if(t < BB*SS){
        int b = t / SS, s = t % SS;
        float acc = ib2[s];
        for(int c = 0; c < CC; c++) acc += h[b][c] * iw2[s*CC + c];
        lg[b][s] = acc;
    }
    __syncthreads();
    if(t < BB){
        float m  = fmaxf(lg[t][0], fmaxf(lg[t][1], lg[t][2]));
        float e0 = expf(lg[t][0]-m), e1 = expf(lg[t][1]-m), e2 = expf(lg[t][2]-m);
        float inv = 1.0f / (e0 + e1 + e2);
        g_wmix[t*SS+0] = e0*inv; g_wmix[t*SS+1] = e1*inv; g_wmix[t*SS+2] = e2*inv;
    }
}

// ---------------- stage 3: q/k/v projection -----------------------------------
__global__ __launch_bounds__(256,2) void k_projT(
    const float* __restrict__ bq, const float* __restrict__ bnq,
    const float* __restrict__ bk_, const float* __restrict__ bnk,
    const float* __restrict__ bv, const float* __restrict__ bnv)
{
    int z = blockIdx.z;
    int which = z / 12;
    int s = (z % 12) >> 2;
    int b = z & 3;
    const __nv_bfloat16* W; const float *bias, *bn; __nv_bfloat16* out;
    if(which == 0){ W = g_wq_bf; bias = bq;  bn = bnq; out = g_q; }
    else if(which == 1){ W = g_wk_bf; bias = bk_; bn = bnk; out = g_k; }
    else { W = g_wv_bf; bias = bv; bn = bnv; out = g_v; }
    W += s * CC * CC;
    const __nv_bfloat16* X = g_x_bf + (size_t)(s*BB+b)*CC*HW;
    __nv_bfloat16*       O = out    + (size_t)(s*BB+b)*CC*HW;
    int m0 = blockIdx.y * 128;
    int n0 = blockIdx.x * 128;
    int lda = CC; size_t strideB = HW;

    GEMM_PRE();
    #define APTR(it) (W + (size_t)m0*CC + (it)*32)
    #define BPTR(it) (X + (size_t)(it)*32*HW + n0)
    GEMM_LOOP(8, APTR, BPTR)
    #undef APTR
    #undef BPTR
    #pragma unroll
    for(int mi = 0; mi < 4; mi++){
        int r0 = m0 + warp_m*64 + mi*16 + g;
        int r1 = r0 + 8;
        float sc0 = bn[(s*4+0)*CC+r0] * rsqrtf(bn[(s*4+3)*CC+r0] + EPSf);
        float sc1 = bn[(s*4+0)*CC+r1] * rsqrtf(bn[(s*4+3)*CC+r1] + EPSf);
        float be0 = bn[(s*4+1)*CC+r0], be1 = bn[(s*4+1)*CC+r1];
        float mu0 = bn[(s*4+2)*CC+r0], mu1 = bn[(s*4+2)*CC+r1];
        float bi0 = bias[s*CC+r0], bi1 = bias[s*CC+r1];
        #pragma unroll
        for(int ni = 0; ni < 4; ni++){
            int nc = n0 + warp_n*32 + ni*8 + tg*2;
            *(__nv_bfloat162*)&O[(size_t)r0*HW + nc] =
                pk2(gelu_f((acc[mi][ni][0] + bi0 - mu0)*sc0 + be0),
                    gelu_f((acc[mi][ni][1] + bi0 - mu0)*sc0 + be0));
            *(__nv_bfloat162*)&O[(size_t)r1*HW + nc] =
                pk2(gelu_f((acc[mi][ni][2] + bi1 - mu1)*sc1 + be1),
                    gelu_f((acc[mi][ni][3] + bi1 - mu1)*sc1 + be1));
        }
    }
}

// ---------------- stage 4: attn_in projection ---------------------------------
__global__ __launch_bounds__(256,2) void k_attninT(const float* __restrict__ aib)
{
    int z = blockIdx.z;
    int which = z / 12;
    int s = (z % 12) >> 2;
    int b = z & 3;
    const __nv_bfloat16* W = g_aiw_bf + which * CC * CC;
    const float* bias = aib + which * CC;
    const __nv_bfloat16* Xg; __nv_bfloat16* Og;
    if(which == 0){ Xg = g_q; Og = g_qt; }
    else if(which == 1){ Xg = g_k; Og = g_kt; }
    else { Xg = g_v; Og = g_vt; }
    const __nv_bfloat16* X = Xg + (size_t)(s*BB+b)*CC*HW;
    __nv_bfloat16*       O = Og + (size_t)(s*BB+b)*CC*HW;
    int m0 = blockIdx.y * 128;
    int n0 = blockIdx.x * 128;
    int lda = CC; size_t strideB = HW;

    GEMM_PRE();
    #define APTR(it) (W + (size_t)m0*CC + (it)*32)
    #define BPTR(it) (X + (size_t)(it)*32*HW + n0)
    GEMM_LOOP(8, APTR, BPTR)
    #undef APTR
    #undef BPTR
    #pragma unroll
    for(int mi = 0; mi < 4; mi++){
        int r0 = m0 + warp_m*64 + mi*16 + g;
        int r1 = r0 + 8;
        float bi0 = bias[r0], bi1 = bias[r1];
        #pragma unroll
        for(int ni = 0; ni < 4; ni++){
            int nc = n0 + warp_n*32 + ni*8 + tg*2;
            *(__nv_bfloat162*)&O[(size_t)r0*HW + nc] =
                pk2(acc[mi][ni][0] + bi0, acc[mi][ni][1] + bi0);
            *(__nv_bfloat162*)&O[(size_t)r1*HW + nc] =
                pk2(acc[mi][ni][2] + bi1, acc[mi][ni][3] + bi1);
        }
    }
}

// ---------------- stage 5: tiny attention over S=3 (+ wmix fold) --------------
__global__ void k_attn(){
    int n = blockIdx.x * blockDim.x + threadIdx.x;
    int head = blockIdx.y;
    int b = n >> 12, p = n & 4095;
    int off0 = ((0*BB+b)*CC)*HW + p;
    int off1 = ((1*BB+b)*CC)*HW + p;
    int off2 = ((2*BB+b)*CC)*HW + p;
    int cbase = head * 32;

    float sc[3][3];
    #pragma unroll
    for(int i=0;i<3;i++){
        #pragma unroll
        for(int j=0;j<3;j++) sc[i][j]=0.f; }

    #pragma unroll 8
    for(int d = 0; d < 32; d++){
        int co = (cbase + d) * HW;
        float q0=__bfloat162float(g_qt[off0+co]), q1=__bfloat162float(g_qt[off1+co]), q2=__bfloat162float(g_qt[off2+co]);
        float k0=__bfloat162float(g_kt[off0+co]), k1=__bfloat162float(g_kt[off1+co]), k2=__bfloat162float(g_kt[off2+co]);
        sc[0][0]+=q0*k0; sc[0][1]+=q0*k1; sc[0][2]+=q0*k2;
        sc[1][0]+=q1*k0; sc[1][1]+=q1*k1; sc[1][2]+=q1*k2;
        sc[2][0]+=q2*k0; sc[2][1]+=q2*k1; sc[2][2]+=q2*k2;
    }
    const float scale = 0.17677669529663688f;
    float at[3][3];
    #pragma unroll
    for(int s_ = 0; s_ < 3; s_++){
        float a0 = sc[s_][0]*scale, a1 = sc[s_][1]*scale, a2 = sc[s_][2]*scale;
        float m = fmaxf(a0, fmaxf(a1, a2));
        float e0 = expf(a0-m), e1 = expf(a1-m), e2 = expf(a2-m);
        float inv = 1.0f / (e0+e1+e2);
        at[s_][0]=e0*inv; at[s_][1]=e1*inv; at[s_][2]=e2*inv;
    }
    float w0 = g_wmix[b*3+0], w1 = g_wmix[b*3+1], w2 = g_wmix[b*3+2];
    #pragma unroll 8
    for(int d = 0; d < 32; d++){
        int co = (cbase + d) * HW;
        float v0=__bfloat162float(g_vt[off0+co]), v1=__bfloat162float(g_vt[off1+co]), v2=__bfloat162float(g_vt[off2+co]);
        g_o[off0+co] = __float2bfloat16(w0*(at[0][0]*v0 + at[0][1]*v1 + at[0][2]*v2));
        g_o[off1+co] = __float2bfloat16(w1*(at[1][0]*v0 + at[1][1]*v1 + at[1][2]*v2));
        g_o[off2+co] = __float2bfloat16(w2*(at[2][0]*v0 + at[2][1]*v1 + at[2][2]*v2));
    }
}

// ---------------- stage 6: attn_out GEMM (K=768, pre-scaled B) -----------------
__global__ __launch_bounds__(256,2) void k_outT(const float* __restrict__ bo)
{
    int b = blockIdx.z;
    int m0 = blockIdx.y * 128;
    int n0 = blockIdx.x * 128;
    int lda = CC; size_t strideB = HW;

    GEMM_PRE();
    #define APTR(it) (g_aow_bf + (size_t)m0*CC + (((it)*32) & 255))
    #define BPTR(it) (g_o + (size_t)(((((it)*32) >> 8)*BB + b)*CC + (((it)*32) & 255))*HW + n0)
    GEMM_LOOP(24, APTR, BPTR)
    #undef APTR
    #undef BPTR
    #pragma unroll
    for(int mi = 0; mi < 4; mi++){
        int r0 = m0 + warp_m*64 + mi*16 + g;
        int r1 = r0 + 8;
        float bi0 = bo[r0], bi1 = bo[r1];
        #pragma unroll
        for(int ni = 0; ni < 4; ni++){
            int nc = n0 + warp_n*32 + ni*8 + tg*2;
            *(__nv_bfloat162*)&g_integr[(size_t)(b*CC+r0)*HW + nc] =
                pk2(acc[mi][ni][0] + bi0, acc[mi][ni][1] + bi0);
            *(__nv_bfloat162*)&g_integr[(size_t)(b*CC+r1)*HW + nc] =
                pk2(acc[mi][ni][2] + bi1, acc[mi][ni][3] + bi1);
        }
    }
}

// ---------------- stage 7: 3x3 conv as GEMM (K=2304) ---------------------------
__device__ __forceinline__ void gatherB_conv(uint4 rv[2], int b, int k0, int n0, int tid){
    #pragma unroll
    for(int i = 0; i < 2; i++){
        int id = tid + i*256;
        int k = id >> 4, u = id & 15;
        int kkg = k0 + k;
        int c  = kkg / 9;
        int r9 = kkg - c*9;
        int kh = r9 / 3, kw = r9 - kh*3;
        const unsigned short* src = (const unsigned short*)(g_integr + (size_t)(b*CC + c)*HW);
        unsigned short v[8];
        #pragma unroll
        for(int j = 0; j < 8; j++){
            int pix = n0 + u*8 + j;
            int hh = (pix >> 6) + kh - 1;
            int ww = (pix & 63) + kw - 1;
            unsigned short val = 0;
            if((unsigned)hh < 64u && (unsigned)ww < 64u) val = src[hh*64 + ww];
            v[j] = val;
        }
        rv[i].x = (uint32_t)v[0] | ((uint32_t)v[1] << 16);
        rv[i].y = (uint32_t)v[2] | ((uint32_t)v[3] << 16);
        rv[i].z = (uint32_t)v[4] | ((uint32_t)v[5] << 16);
        rv[i].w = (uint32_t)v[6] | ((uint32_t)v[7] << 16);
    }
}
__device__ __forceinline__ void stsB_conv(uint32_t* smBbuf, const uint4 rv[2], int tid){
    #pragma unroll
    for(int i = 0; i < 2; i++){
        int id = tid + i*256;
        int k = id >> 4, u = id & 15;
        int widx = k*64 + ((u ^ (k&7)) << 2);
        *(uint4*)&smBbuf[widx] = rv[i];
    }
}

__global__ __launch_bounds__(256,2) void k_convT(const float* __restrict__ b1,
                                                 const float* __restrict__ opbn)
{
    int b = blockIdx.z;
    int m0 = blockIdx.y * 128;
    int n0 = blockIdx.x * 128;
    const int lda = CC*9;
    const int nk = (CC*9)/32;   // 72

    GEMM_PRE();
    // prologue: A via cp.async (2 stages), B(0) via gather+STS
    cpA(AsB,        g_cw_bf + (size_t)m0*lda + 0,  lda, tid); CP_COMMIT();
    cpA(AsB + 8192, g_cw_bf + (size_t)m0*lda + 32, lda, tid); CP_COMMIT();
    {
        uint4 rv[2];
        gatherB_conv(rv, b, 0, n0, tid);
        stsB_conv(smB[0], rv, tid);
    }
    for(int it = 0; it < nk; it++){
        if(it + 1 < nk) { CP_WAIT1(); } else { CP_WAIT0(); }
        __syncthreads();
        if(it + 2 < nk){
            int st = (it+2)%3;
            cpA(AsB + st*8192, g_cw_bf + (size_t)m0*lda + (it+2)*32, lda, tid);
            CP_COMMIT();
        }
        uint4 rv[2];
        if(it + 1 < nk) gatherB_conv(rv, b, (it+1)*32, n0, tid);
        int cb = it % 3;
        chunk_mma(AsB + cb*8192, BsB + cb*8192, acc, warp_m, warp_n, lane);
        if(it + 1 < nk) stsB_conv(smB[(it+1)%3], rv, tid);
    }
    #pragma unroll
    for(int mi = 0; mi < 4; mi++){
        int r0 = m0 + warp_m*64 + mi*16 + g;
        int r1 = r0 + 8;
        float sc0 = opbn[0*CC+r0] * rsqrtf(opbn[3*CC+r0] + EPSf);
        float sc1 = opbn[0*CC+r1] * rsqrtf(opbn[3*CC+r1] + EPSf);
        float be0 = opbn[1*CC+r0], be1 = opbn[1*CC+r1];
        float mu0 = opbn[2*CC+r0], mu1 = opbn[2*CC+r1];
        float bi0 = b1[r0], bi1 = b1[r1];
        #pragma unroll
        for(int ni = 0; ni < 4; ni++){
            int nc = n0 + warp_n*32 + ni*8 + tg*2;
            *(__nv_bfloat162*)&g_y2[(size_t)(b*CC+r0)*HW + nc] =
                pk2(gelu_f((acc[mi][ni][0] + bi0 - mu0)*sc0 + be0),
                    gelu_f((acc[mi][ni][1] + bi0 - mu0)*sc0 + be0));
            *(__nv_bfloat162*)&g_y2[(size_t)(b*CC+r1)*HW + nc] =
                pk2(gelu_f((acc[mi][ni][2] + bi1 - mu1)*sc1 + be1),
                    gelu_f((acc[mi][ni][3] + bi1 - mu1)*sc1 + be1));
        }
    }
}

// ---------------- stage 8: final 1x1 + residual --------------------------------
__global__ __launch_bounds__(256,2) void k_finalT(const float* __restrict__ b2,
                                                  const float* __restrict__ x,
                                                  float* __restrict__ out)
{
    int b = blockIdx.z;
    int m0 = blockIdx.y * 128;
    int n0 = blockIdx.x * 128;
    int lda = CC; size_t strideB = HW;

    GEMM_PRE();
    #define APTR(it) (g_w2_bf + (size_t)m0*CC + (it)*32)
    #define BPTR(it) (g_y2 + (size_t)(b*CC + (it)*32)*HW + n0)
    GEMM_LOOP(8, APTR, BPTR)
    #undef APTR
    #undef BPTR
    #pragma unroll
    for(int mi = 0; mi < 4; mi++){
        int r0 = m0 + warp_m*64 + mi*16 + g;
        int r1 = r0 + 8;
        float bi0 = b2[r0], bi1 = b2[r1];
        const float* res0 = x + (size_t)((1*BB+b)*CC + r0)*HW;
        const float* res1 = x + (size_t)((1*BB+b)*CC + r1)*HW;
        #pragma unroll
        for(int ni = 0; ni < 4; ni++){
            int nc = n0 + warp_n*32 + ni*8 + tg*2;
            float2 a0 = *(const float2*)&res0[nc];
            float2 a1 = *(const float2*)&res1[nc];
            float2 o0, o1;
            o0.x = acc[mi][ni][0] + bi0 + a0.x; o0.y = acc[mi][ni][1] + bi0 + a0.y;
            o1.x = acc[mi][ni][2] + bi1 + a1.x; o1.y = acc[mi][ni][3] + bi1 + a1.y;
            *(float2*)&out[(size_t)(b*CC+r0)*HW + nc] = o0;
            *(float2*)&out[(size_t)(b*CC+r1)*HW + nc] = o1;
        }
    }
}

// ---------------- launcher ------------------------------------------------------
extern "C" void kernel_launch(void* const* d_in, const int* in_sizes, int n_in,
                              void* d_out, int out_size)
{
    (void)in_sizes; (void)n_in; (void)out_size;
    const float* x   = (const float*)d_in[0];
    const float* Wq  = (const float*)d_in[1];
    const float* bq  = (const float*)d_in[2];
    const float* bnq = (const float*)d_in[3];
    const float* Wk_ = (const float*)d_in[4];
    const float* bk_ = (const float*)d_in[5];
    const float* bnk = (const float*)d_in[6];
    const float* Wv  = (const float*)d_in[7];
    const float* bv  = (const float*)d_in[8];
    const float* bnv = (const float*)d_in[9];
    const float* iw1 = (const float*)d_in[10];
    const float* ib1 = (const float*)d_in[11];
    const float* iw2 = (const float*)d_in[12];
    const float* ib2 = (const float*)d_in[13];
    const float* aiw = (const float*)d_in[14];
    const float* aib = (const float*)d_in[15];
    const float* aow = (const float*)d_in[16];
    const float* aob = (const float*)d_in[17];
    const float* cw  = (const float*)d_in[18];
    const float* cb1 = (const float*)d_in[19];
    const float* cbn = (const float*)d_in[20];
    const float* w2  = (const float*)d_in[21];
    const float* b2  = (const float*)d_in[22];
    float* out = (float*)d_out;

    k_cvtW<<<1472, 256>>>(Wq, Wk_, Wv, aiw, aow, cw, w2);
    k_cvtX<<<6144, 256>>>(x);
    k_pool<<<SS*BB*CC, 256>>>(x);
    k_imp<<<1, 256>>>(iw1, ib1, iw2, ib2);
    k_projT<<<dim3(32,2,36), 256>>>(bq, bnq, bk_, bnk, bv, bnv);
    k_attninT<<<dim3(32,2,36), 256>>>(aib);
    k_attn<<<dim3(64,8), 256>>>();
    k_outT<<<dim3(32,2,4), 256>>>(aob);
    k_convT<<<dim3(32,2,4), 256>>>(cb1, cbn);
    k_finalT<<<dim3(32,2,4), 256>>>(b2, x, out);
}

// round 8
// speedup vs baseline: 3.3670x; 1.3200x over previous
#include <cuda_runtime.h>
#include <cuda_bf16.h>
#include <cstdint>
#include <math.h>

#define SS 3
#define BB 4
#define CC 256
#define HW 4096
#define EPSf 1e-5f

// ---------------- scratch ----------------------------------------------------
__device__ float g_pooled[BB*SS*CC];
__device__ float g_h[BB*CC];
__device__ float g_wmix[BB*SS];
__device__ __align__(256) __nv_bfloat16 g_x_bf[SS*BB*CC*HW];
__device__ __align__(256) __nv_bfloat16 g_q [SS*BB*CC*HW];
__device__ __align__(256) __nv_bfloat16 g_k [SS*BB*CC*HW];
__device__ __align__(256) __nv_bfloat16 g_v [SS*BB*CC*HW];
__device__ __align__(256) __nv_bfloat16 g_qt[SS*BB*CC*HW];
__device__ __align__(256) __nv_bfloat16 g_kt[SS*BB*CC*HW];
__device__ __align__(256) __nv_bfloat16 g_vt[SS*BB*CC*HW];
__device__ __align__(256) __nv_bfloat16 g_o [SS*BB*CC*HW];
__device__ __align__(256) __nv_bfloat16 g_integr[BB*CC*HW];
__device__ __align__(256) __nv_bfloat16 g_y2[BB*CC*HW];
// bf16 weights
__device__ __align__(256) __nv_bfloat16 g_wq_bf [SS*CC*CC];
__device__ __align__(256) __nv_bfloat16 g_wk_bf [SS*CC*CC];
__device__ __align__(256) __nv_bfloat16 g_wv_bf [SS*CC*CC];
__device__ __align__(256) __nv_bfloat16 g_aiw_bf[3*CC*CC];
__device__ __align__(256) __nv_bfloat16 g_aow_bf[CC*CC];
__device__ __align__(256) __nv_bfloat16 g_cw_bf [CC*CC*9];
__device__ __align__(256) __nv_bfloat16 g_w2_bf [CC*CC];

__device__ __forceinline__ float gelu_f(float x){
    return 0.5f * x * (1.0f + erff(x * 0.70710678118654752f));
}
__device__ __forceinline__ uint32_t pkbf(float lo, float hi){
    __nv_bfloat162 h = __float22bfloat162_rn(make_float2(lo, hi));
    return *(uint32_t*)&h;
}
__device__ __forceinline__ __nv_bfloat162 pk2(float lo, float hi){
    return __float22bfloat162_rn(make_float2(lo, hi));
}
__device__ __forceinline__ void mma16(float c[4], const uint32_t a[4], const uint32_t b[2]){
    asm volatile(
        "mma.sync.aligned.m16n8k16.row.col.f32.bf16.bf16.f32 "
        "{%0,%1,%2,%3}, {%4,%5,%6,%7}, {%8,%9}, {%0,%1,%2,%3};"
        : "+f"(c[0]), "+f"(c[1]), "+f"(c[2]), "+f"(c[3])
        : "r"(a[0]), "r"(a[1]), "r"(a[2]), "r"(a[3]), "r"(b[0]), "r"(b[1]));
}

#define CP16(dst, src) asm volatile("cp.async.cg.shared.global [%0], [%1], 16;" :: "r"(dst), "l"(src))
#define CP_COMMIT()    asm volatile("cp.async.commit_group;" ::: "memory")
#define CP_WAIT1()     asm volatile("cp.async.wait_group 1;" ::: "memory")
#define CP_WAIT0()     asm volatile("cp.async.wait_group 0;" ::: "memory")
#define LDSM_X4(r, addr) \
    asm volatile("ldmatrix.sync.aligned.m8n8.x4.shared.b16 {%0,%1,%2,%3}, [%4];" \
        : "=r"((r)[0]), "=r"((r)[1]), "=r"((r)[2]), "=r"((r)[3]) : "r"(addr))
#define LDSM_X4T(r, addr) \
    asm volatile("ldmatrix.sync.aligned.m8n8.x4.trans.shared.b16 {%0,%1,%2,%3}, [%4];" \
        : "=r"((r)[0]), "=r"((r)[1]), "=r"((r)[2]), "=r"((r)[3]) : "r"(addr))

// ---------------- GEMM core ---------------------------------------------------
// CTA tile 128(M) x 128(N), BK=32 bf16, 256 thr = 8 warps (2M x 4N), warp 64x32.

__device__ __forceinline__ void cpA(uint32_t As, const __nv_bfloat16* W, int lda, int tid){
    #pragma unroll
    for(int i = 0; i < 2; i++){
        int id = tid + i*256;
        int m = id >> 2, u = id & 3;
        const __nv_bfloat16* src = W + (size_t)m*lda + u*8;
        uint32_t unit8 = (uint32_t)((((m&1)<<2) | u) ^ ((m>>1)&7));
        CP16(As + ((m>>1)<<7) + (unit8<<4), src);
    }
}
__device__ __forceinline__ void cpB(uint32_t Bs, const __nv_bfloat16* X, size_t stride, int tid){
    #pragma unroll
    for(int i = 0; i < 2; i++){
        int id = tid + i*256;
        int k = id >> 4, u = id & 15;
        const __nv_bfloat16* src = X + (size_t)k*stride + u*8;
        CP16(Bs + (k<<8) + (((uint32_t)(u ^ (k&7)))<<4), src);
    }
}

__device__ __forceinline__ void chunk_mma(uint32_t As, uint32_t Bs, float acc[4][4][4],
                                          int warp_m, int warp_n, int lane){
    int ml = lane & 15, sel = lane >> 4;
    #pragma unroll
    for(int kb = 0; kb < 2; kb++){
        uint32_t a[4][4], bb[2][4];
        #pragma unroll
        for(int mt = 0; mt < 4; mt++){
            int m = warp_m*64 + mt*16 + ml;
            int unit = kb*2 + sel;
            uint32_t addr = As + ((m>>1)<<7) +
                ((uint32_t)(((((m&1)<<2) | unit) ^ ((m>>1)&7)))<<4);
            LDSM_X4(a[mt], addr);
        }
        #pragma unroll
        for(int np = 0; np < 2; np++){
            int kk = kb*16 + ml;
            int u = warp_n*4 + np*2 + sel;
            uint32_t addr = Bs + (kk<<8) + (((uint32_t)(u ^ (kk&7)))<<4);
            LDSM_X4T(bb[np], addr);
        }
        #pragma unroll
        for(int mt = 0; mt < 4; mt++)
            #pragma unroll
            for(int nt = 0; nt < 4; nt++)
                mma16(acc[mt][nt], a[mt], bb[nt>>1] + ((nt&1)<<1));
    }
}

#define GEMM_PRE() \
    __shared__ __align__(16) uint32_t smA[3][2048]; \
    __shared__ __align__(16) uint32_t smB[3][2048]; \
    uint32_t AsB = (uint32_t)__cvta_generic_to_shared(smA); \
    uint32_t BsB = (uint32_t)__cvta_generic_to_shared(smB); \
    float acc[4][4][4]; \
    _Pragma("unroll") \
    for(int i=0;i<4;i++) _Pragma("unroll") for(int j=0;j<4;j++) _Pragma("unroll") for(int r=0;r<4;r++) acc[i][j][r]=0.f; \
    int tid = threadIdx.x; \
    int wid = tid >> 5, lane = tid & 31; \
    int warp_m = wid >> 2, warp_n = wid & 3; \
    int g = lane >> 2, tg = lane & 3; (void)g; (void)tg;

#define GEMM_LOOP(NK, APTR, BPTR) \
    cpA(AsB,        APTR(0), lda, tid); cpB(BsB,        BPTR(0), strideB, tid); CP_COMMIT(); \
    cpA(AsB + 8192, APTR(1), lda, tid); cpB(BsB + 8192, BPTR(1), strideB, tid); CP_COMMIT(); \
    for(int it = 0; it < (NK); it++){ \
        if(it + 1 < (NK)) { CP_WAIT1(); } else { CP_WAIT0(); } \
        __syncthreads(); \
        if(it + 2 < (NK)){ \
            int st = (it+2)%3; \
            cpA(AsB + st*8192, APTR(it+2), lda, tid); \
            cpB(BsB + st*8192, BPTR(it+2), strideB, tid); \
            CP_COMMIT(); \
        } \
        int cb = it % 3; \
        chunk_mma(AsB + cb*8192, BsB + cb*8192, acc, warp_m, warp_n, lane); \
    }

// ---------------- prep: weight conversion -------------------------------------
__global__ void k_cvtW(const float* Wq, const float* Wk_, const float* Wv,
                       const float* aiw, const float* aow, const float* cw, const float* w2){
    int i = (blockIdx.x*256 + threadIdx.x) * 4;
    const float* src; __nv_bfloat16* dst; int off;
    if(i < 196608){ src=Wq;  dst=g_wq_bf;  off=i; }
    else if(i <  393216){ src=Wk_; dst=g_wk_bf;  off=i-196608; }
    else if(i <  589824){ src=Wv;  dst=g_wv_bf;  off=i-393216; }
    else if(i <  786432){ src=aiw; dst=g_aiw_bf; off=i-589824; }
    else if(i <  851968){ src=aow; dst=g_aow_bf; off=i-786432; }
    else if(i < 1441792){ src=cw;  dst=g_cw_bf;  off=i-851968; }
    else if(i < 1507328){ src=w2;  dst=g_w2_bf;  off=i-1441792; }
    else return;
    float4 v = *(const float4*)(src + off);
    uint2 o; o.x = pkbf(v.x, v.y); o.y = pkbf(v.z, v.w);
    *(uint2*)(dst + off) = o;
}

// ---------------- fused: x -> bf16 + channel mean pool -------------------------
// one block per channel (4096 floats); converts + reduces in one pass
__global__ void k_cvtX(const float* __restrict__ x){
    int id = blockIdx.x;                // (s*BB+b)*CC + c
    int c = id & 255;
    int b = (id >> 8) & 3;
    int s = id >> 10;
    size_t base = (size_t)id * HW;
    const float4* src = (const float4*)(x + base);
    int t = threadIdx.x;
    float sum = 0.f;
    #pragma unroll
    for(int i = 0; i < 4; i++){
        int idx = t*4 + i*1024;         // 4 floats per load, 4 loads
        float4 v = src[idx >> 2];
        sum += v.x + v.y + v.z + v.w;
        uint2 o; o.x = pkbf(v.x, v.y); o.y = pkbf(v.z, v.w);
        *(uint2*)(g_x_bf + base + idx) = o;
    }
    __shared__ float red[8];
    #pragma unroll
    for(int o = 16; o > 0; o >>= 1) sum += __shfl_down_sync(0xffffffffu, sum, o);
    if((t & 31) == 0) red[t >> 5] = sum;
    __syncthreads();
    if(t == 0){
        float tt = 0.f;
        #pragma unroll
        for(int i = 0; i < 8; i++) tt += red[i];
        g_pooled[(b*SS + s)*CC + c] = tt * (1.0f / HW);
    }
}

// ---------------- importance MLP: parallel hidden layer ------------------------
// one warp per hidden channel; computes all 4 batches' dots (K=768)
__global__ void k_imp1(const float* __restrict__ iw1, const float* __restrict__ ib1){
    int warp = (blockIdx.x * 256 + threadIdx.x) >> 5;   // 0..255
    int lane = threadIdx.x & 31;
    const float* row = iw1 + (size_t)warp * (SS*CC);
    float a0=0.f, a1=0.f, a2=0.f, a3=0.f;
    for(int i = lane; i < SS*CC; i += 32){
        float w = row[i];
        a0 += w * g_pooled[0*(SS*CC)+i];
        a1 += w * g_pooled[1*(SS*CC)+i];
        a2 += w * g_pooled[2*(SS*CC)+i];
        a3 += w * g_pooled[3*(SS*CC)+i];
    }
    #pragma unroll
    for(int o = 16; o > 0; o >>= 1){
        a0 += __shfl_down_sync(0xffffffffu, a0, o);
        a1 += __shfl_down_sync(0xffffffffu, a1, o);
        a2 += __shfl_down_sync(0xffffffffu, a2, o);
        a3 += __shfl_down_sync(0xffffffffu, a3, o);
    }
    if(lane == 0){
        float bi = ib1[warp];
        g_h[0*CC+warp] = gelu_f(a0 + bi);
        g_h[1*CC+warp] = gelu_f(a1 + bi);
        g_h[2*CC+warp] = gelu_f(a2 + bi);
        g_h[3*CC+warp] = gelu_f(a3 + bi);
    }
}
// logits + softmax (tiny)
__global__ void k_imp2(const float* __restrict__ iw2, const float* __restrict__ ib2){
    __shared__ float lg[BB][SS];
    int t = threadIdx.x;
    if(t < BB*SS){
        int b = t / SS, s = t % SS;
        float acc = ib2[s];
        for(int c = 0; c < CC; c++) acc += g_h[b*CC+c] * iw2[s*CC + c];
        lg[b][s] = acc;
    }
    __syncthreads();
    if(t < BB){
        float m  = fmaxf(lg[t][0], fmaxf(lg[t][1], lg[t][2]));
        float e0 = expf(lg[t][0]-m), e1 = expf(lg[t][1]-m), e2 = expf(lg[t][2]-m);
        float inv = 1.0f / (e0 + e1 + e2);
        g_wmix[t*SS+0] = e0*inv; g_wmix[t*SS+1] = e1*inv; g_wmix[t*SS+2] = e2*inv;
    }
}

// ---------------- stage 3: q/k/v projection -----------------------------------
__global__ __launch_bounds__(256,2) void k_projT(
    const float* __restrict__ bq, const float* __restrict__ bnq,
    const float* __restrict__ bk_, const float* __restrict__ bnk,
    const float* __restrict__ bv, const float* __restrict__ bnv)
{
    int z = blockIdx.z;
    int which = z / 12;
    int s = (z % 12) >> 2;
    int b = z & 3;
    const __nv_bfloat16* W; const float *bias, *bn; __nv_bfloat16* out;
    if(which == 0){ W = g_wq_bf; bias = bq;  bn = bnq; out = g_q; }
    else if(which == 1){ W = g_wk_bf; bias = bk_; bn = bnk; out = g_k; }
    else { W = g_wv_bf; bias = bv; bn = bnv; out = g_v; }
    W += s * CC * CC;
    const __nv_bfloat16* X = g_x_bf + (size_t)(s*BB+b)*CC*HW;
    __nv_bfloat16*       O = out    + (size_t)(s*BB+b)*CC*HW;
    int m0 = blockIdx.y * 128;
    int n0 = blockIdx.x * 128;
    int lda = CC; size_t strideB = HW;

    GEMM_PRE();
    #define APTR(it) (W + (size_t)m0*CC + (it)*32)
    #define BPTR(it) (X + (size_t)(it)*32*HW + n0)
    GEMM_LOOP(8, APTR, BPTR)
    #undef APTR
    #undef BPTR
    #pragma unroll
    for(int mi = 0; mi < 4; mi++){
        int r0 = m0 + warp_m*64 + mi*16 + g;
        int r1 = r0 + 8;
        float sc0 = bn[(s*4+0)*CC+r0] * rsqrtf(bn[(s*4+3)*CC+r0] + EPSf);
        float sc1 = bn[(s*4+0)*CC+r1] * rsqrtf(bn[(s*4+3)*CC+r1] + EPSf);
        float be0 = bn[(s*4+1)*CC+r0], be1 = bn[(s*4+1)*CC+r1];
        float mu0 = bn[(s*4+2)*CC+r0], mu1 = bn[(s*4+2)*CC+r1];
        float bi0 = bias[s*CC+r0], bi1 = bias[s*CC+r1];
        #pragma unroll
        for(int ni = 0; ni < 4; ni++){
            int nc = n0 + warp_n*32 + ni*8 + tg*2;
            *(__nv_bfloat162*)&O[(size_t)r0*HW + nc] =
                pk2(gelu_f((acc[mi][ni][0] + bi0 - mu0)*sc0 + be0),
                    gelu_f((acc[mi][ni][1] + bi0 - mu0)*sc0 + be0));
            *(__nv_bfloat162*)&O[(size_t)r1*HW + nc] =
                pk2(gelu_f((acc[mi][ni][2] + bi1 - mu1)*sc1 + be1),
                    gelu_f((acc[mi][ni][3] + bi1 - mu1)*sc1 + be1));
        }
    }
}

// ---------------- stage 4: attn_in projection ---------------------------------
__global__ __launch_bounds__(256,2) void k_attninT(const float* __restrict__ aib)
{
    int z = blockIdx.z;
    int which = z / 12;
    int s = (z % 12) >> 2;
    int b = z & 3;
    const __nv_bfloat16* W = g_aiw_bf + which * CC * CC;
    const float* bias = aib + which * CC;
    const __nv_bfloat16* Xg; __nv_bfloat16* Og;
    if(which == 0){ Xg = g_q; Og = g_qt; }
    else if(which == 1){ Xg = g_k; Og = g_kt; }
    else { Xg = g_v; Og = g_vt; }
    const __nv_bfloat16* X = Xg + (size_t)(s*BB+b)*CC*HW;
    __nv_bfloat16*       O = Og + (size_t)(s*BB+b)*CC*HW;
    int m0 = blockIdx.y * 128;
    int n0 = blockIdx.x * 128;
    int lda = CC; size_t strideB = HW;

    GEMM_PRE();
    #define APTR(it) (W + (size_t)m0*CC + (it)*32)
    #define BPTR(it) (X + (size_t)(it)*32*HW + n0)
    GEMM_LOOP(8, APTR, BPTR)
    #undef APTR
    #undef BPTR
    #pragma unroll
    for(int mi = 0; mi < 4; mi++){
        int r0 = m0 + warp_m*64 + mi*16 + g;
        int r1 = r0 + 8;
        float bi0 = bias[r0], bi1 = bias[r1];
        #pragma unroll
        for(int ni = 0; ni < 4; ni++){
            int nc = n0 + warp_n*32 + ni*8 + tg*2;
            *(__nv_bfloat162*)&O[(size_t)r0*HW + nc] =
                pk2(acc[mi][ni][0] + bi0, acc[mi][ni][1] + bi0);
            *(__nv_bfloat162*)&O[(size_t)r1*HW + nc] =
                pk2(acc[mi][ni][2] + bi1, acc[mi][ni][3] + bi1);
        }
    }
}

// ---------------- stage 5: tiny attention over S=3 (+ wmix fold) --------------
__global__ void k_attn(){
    int n = blockIdx.x * blockDim.x + threadIdx.x;
    int head = blockIdx.y;
    int b = n >> 12, p = n & 4095;
    int off0 = ((0*BB+b)*CC)*HW + p;
    int off1 = ((1*BB+b)*CC)*HW + p;
    int off2 = ((2*BB+b)*CC)*HW + p;
    int cbase = head * 32;

    float sc[3][3];
    #pragma unroll
    for(int i=0;i<3;i++){
        #pragma unroll
        for(int j=0;j<3;j++) sc[i][j]=0.f; }

    #pragma unroll 8
    for(int d = 0; d < 32; d++){
        int co = (cbase + d) * HW;
        float q0=__bfloat162float(g_qt[off0+co]), q1=__bfloat162float(g_qt[off1+co]), q2=__bfloat162float(g_qt[off2+co]);
        float k0=__bfloat162float(g_kt[off0+co]), k1=__bfloat162float(g_kt[off1+co]), k2=__bfloat162float(g_kt[off2+co]);
        sc[0][0]+=q0*k0; sc[0][1]+=q0*k1; sc[0][2]+=q0*k2;
        sc[1][0]+=q1*k0; sc[1][1]+=q1*k1; sc[1][2]+=q1*k2;
        sc[2][0]+=q2*k0; sc[2][1]+=q2*k1; sc[2][2]+=q2*k2;
    }
    const float scale = 0.17677669529663688f;
    float at[3][3];
    #pragma unroll
    for(int s_ = 0; s_ < 3; s_++){
        float a0 = sc[s_][0]*scale, a1 = sc[s_][1]*scale, a2 = sc[s_][2]*scale;
        float m = fmaxf(a0, fmaxf(a1, a2));
        float e0 = expf(a0-m), e1 = expf(a1-m), e2 = expf(a2-m);
        float inv = 1.0f / (e0+e1+e2);
        at[s_][0]=e0*inv; at[s_][1]=e1*inv; at[s_][2]=e2*inv;
    }
    float w0 = g_wmix[b*3+0], w1 = g_wmix[b*3+1], w2 = g_wmix[b*3+2];
    #pragma unroll 8
    for(int d = 0; d < 32; d++){
        int co = (cbase + d) * HW;
        float v0=__bfloat162float(g_vt[off0+co]), v1=__bfloat162float(g_vt[off1+co]), v2=__bfloat162float(g_vt[off2+co]);
        g_o[off0+co] = __float2bfloat16(w0*(at[0][0]*v0 + at[0][1]*v1 + at[0][2]*v2));
        g_o[off1+co] = __float2bfloat16(w1*(at[1][0]*v0 + at[1][1]*v1 + at[1][2]*v2));
        g_o[off2+co] = __float2bfloat16(w2*(at[2][0]*v0 + at[2][1]*v1 + at[2][2]*v2));
    }
}

// ---------------- stage 6: attn_out GEMM (K=768, pre-scaled B) -----------------
__global__ __launch_bounds__(256,2) void k_outT(const float* __restrict__ bo)
{
    int b = blockIdx.z;
    int m0 = blockIdx.y * 128;
    int n0 = blockIdx.x * 128;
    int lda = CC; size_t strideB = HW;

    GEMM_PRE();
    #define APTR(it) (g_aow_bf + (size_t)m0*CC + (((it)*32) & 255))
    #define BPTR(it) (g_o + (size_t)(((((it)*32) >> 8)*BB + b)*CC + (((it)*32) & 255))*HW + n0)
    GEMM_LOOP(24, APTR, BPTR)
    #undef APTR
    #undef BPTR
    #pragma unroll
    for(int mi = 0; mi < 4; mi++){
        int r0 = m0 + warp_m*64 + mi*16 + g;
        int r1 = r0 + 8;
        float bi0 = bo[r0], bi1 = bo[r1];
        #pragma unroll
        for(int ni = 0; ni < 4; ni++){
            int nc = n0 + warp_n*32 + ni*8 + tg*2;
            *(__nv_bfloat162*)&g_integr[(size_t)(b*CC+r0)*HW + nc] =
                pk2(acc[mi][ni][0] + bi0, acc[mi][ni][1] + bi0);
            *(__nv_bfloat162*)&g_integr[(size_t)(b*CC+r1)*HW + nc] =
                pk2(acc[mi][ni][2] + bi1, acc[mi][ni][3] + bi1);
        }
    }
}

// ---------------- stage 7: 3x3 conv as GEMM (K=2304) ---------------------------
__device__ __forceinline__ void gatherB_conv(uint4 rv[2], int b, int k0, int n0, int tid){
    #pragma unroll
    for(int i = 0; i < 2; i++){
        int id = tid + i*256;
        int k = id >> 4, u = id & 15;
        int kkg = k0 + k;
        int c  = kkg / 9;
        int r9 = kkg - c*9;
        int kh = r9 / 3, kw = r9 - kh*3;
        const unsigned short* src = (const unsigned short*)(g_integr + (size_t)(b*CC + c)*HW);
        unsigned short v[8];
        #pragma unroll
        for(int j = 0; j < 8; j++){
            int pix = n0 + u*8 + j;
            int hh = (pix >> 6) + kh - 1;
            int ww = (pix & 63) + kw - 1;
            unsigned short val = 0;
            if((unsigned)hh < 64u && (unsigned)ww < 64u) val = src[hh*64 + ww];
            v[j] = val;
        }
        rv[i].x = (uint32_t)v[0] | ((uint32_t)v[1] << 16);
        rv[i].y = (uint32_t)v[2] | ((uint32_t)v[3] << 16);
        rv[i].z = (uint32_t)v[4] | ((uint32_t)v[5] << 16);
        rv[i].w = (uint32_t)v[6] | ((uint32_t)v[7] << 16);
    }
}
__device__ __forceinline__ void stsB_conv(uint32_t* smBbuf, const uint4 rv[2], int tid){
    #pragma unroll
    for(int i = 0; i < 2; i++){
        int id = tid + i*256;
        int k = id >> 4, u = id & 15;
        int widx = k*64 + ((u ^ (k&7)) << 2);
        *(uint4*)&smBbuf[widx] = rv[i];
    }
}

__global__ __launch_bounds__(256,2) void k_convT(const float* __restrict__ b1,
                                                 const float* __restrict__ opbn)
{
    int b = blockIdx.z;
    int m0 = blockIdx.y * 128;
    int n0 = blockIdx.x * 128;
    const int lda = CC*9;
    const int nk = (CC*9)/32;   // 72

    GEMM_PRE();
    cpA(AsB,        g_cw_bf + (size_t)m0*lda + 0,  lda, tid); CP_COMMIT();
    cpA(AsB + 8192, g_cw_bf + (size_t)m0*lda + 32, lda, tid); CP_COMMIT();
    {
        uint4 rv[2];
        gatherB_conv(rv, b, 0, n0, tid);
        stsB_conv(smB[0], rv, tid);
    }
    for(int it = 0; it < nk; it++){
        if(it + 1 < nk) { CP_WAIT1(); } else { CP_WAIT0(); }
        __syncthreads();
        if(it + 2 < nk){
            int st = (it+2)%3;
            cpA(AsB + st*8192, g_cw_bf + (size_t)m0*lda + (it+2)*32, lda, tid);
            CP_COMMIT();
        }
        uint4 rv[2];
        if(it + 1 < nk) gatherB_conv(rv, b, (it+1)*32, n0, tid);
        int cb = it % 3;
        chunk_mma(AsB + cb*8192, BsB + cb*8192, acc, warp_m, warp_n, lane);
        if(it + 1 < nk) stsB_conv(smB[(it+1)%3], rv, tid);
    }
    #pragma unroll
    for(int mi = 0; mi < 4; mi++){
        int r0 = m0 + warp_m*64 + mi*16 + g;
        int r1 = r0 + 8;
        float sc0 = opbn[0*CC+r0] * rsqrtf(opbn[3*CC+r0] + EPSf);
        float sc1 = opbn[0*CC+r1] * rsqrtf(opbn[3*CC+r1] + EPSf);
        float be0 = opbn[1*CC+r0], be1 = opbn[1*CC+r1];
        float mu0 = opbn[2*CC+r0], mu1 = opbn[2*CC+r1];
        float bi0 = b1[r0], bi1 = b1[r1];
        #pragma unroll
        for(int ni = 0; ni < 4; ni++){
            int nc = n0 + warp_n*32 + ni*8 + tg*2;
            *(__nv_bfloat162*)&g_y2[(size_t)(b*CC+r0)*HW + nc] =
                pk2(gelu_f((acc[mi][ni][0] + bi0 - mu0)*sc0 + be0),
                    gelu_f((acc[mi][ni][1] + bi0 - mu0)*sc0 + be0));
            *(__nv_bfloat162*)&g_y2[(size_t)(b*CC+r1)*HW + nc] =
                pk2(gelu_f((acc[mi][ni][2] + bi1 - mu1)*sc1 + be1),
                    gelu_f((acc[mi][ni][3] + bi1 - mu1)*sc1 + be1));
        }
    }
}

// ---------------- stage 8: final 1x1 + residual --------------------------------
__global__ __launch_bounds__(256,2) void k_finalT(const float* __restrict__ b2,
                                                  const float* __restrict__ x,
                                                  float* __restrict__ out)
{
    int b = blockIdx.z;
    int m0 = blockIdx.y * 128;
    int n0 = blockIdx.x * 128;
    int lda = CC; size_t strideB = HW;

    GEMM_PRE();
    #define APTR(it) (g_w2_bf + (size_t)m0*CC + (it)*32)
    #define BPTR(it) (g_y2 + (size_t)(b*CC + (it)*32)*HW + n0)
    GEMM_LOOP(8, APTR, BPTR)
    #undef APTR
    #undef BPTR
    #pragma unroll
    for(int mi = 0; mi < 4; mi++){
        int r0 = m0 + warp_m*64 + mi*16 + g;
        int r1 = r0 + 8;
        float bi0 = b2[r0], bi1 = b2[r1];
        const float* res0 = x + (size_t)((1*BB+b)*CC + r0)*HW;
        const float* res1 = x + (size_t)((1*BB+b)*CC + r1)*HW;
        #pragma unroll
        for(int ni = 0; ni < 4; ni++){
            int nc = n0 + warp_n*32 + ni*8 + tg*2;
            float2 a0 = *(const float2*)&res0[nc];
            float2 a1 = *(const float2*)&res1[nc];
            float2 o0, o1;
            o0.x = acc[mi][ni][0] + bi0 + a0.x; o0.y = acc[mi][ni][1] + bi0 + a0.y;
            o1.x = acc[mi][ni][2] + bi1 + a1.x; o1.y = acc[mi][ni][3] + bi1 + a1.y;
            *(float2*)&out[(size_t)(b*CC+r0)*HW + nc] = o0;
            *(float2*)&out[(size_t)(b*CC+r1)*HW + nc] = o1;
        }
    }
}

// ---------------- launcher ------------------------------------------------------
extern "C" void kernel_launch(void* const* d_in, const int* in_sizes, int n_in,
                              void* d_out, int out_size)
{
    (void)in_sizes; (void)n_in; (void)out_size;
    const float* x   = (const float*)d_in[0];
    const float* Wq  = (const float*)d_in[1];
    const float* bq  = (const float*)d_in[2];
    const float* bnq = (const float*)d_in[3];
    const float* Wk_ = (const float*)d_in[4];
    const float* bk_ = (const float*)d_in[5];
    const float* bnk = (const float*)d_in[6];
    const float* Wv  = (const float*)d_in[7];
    const float* bv  = (const float*)d_in[8];
    const float* bnv = (const float*)d_in[9];
    const float* iw1 = (const float*)d_in[10];
    const float* ib1 = (const float*)d_in[11];
    const float* iw2 = (const float*)d_in[12];
    const float* ib2 = (const float*)d_in[13];
    const float* aiw = (const float*)d_in[14];
    const float* aib = (const float*)d_in[15];
    const float* aow = (const float*)d_in[16];
    const float* aob = (const float*)d_in[17];
    const float* cw  = (const float*)d_in[18];
    const float* cb1 = (const float*)d_in[19];
    const float* cbn = (const float*)d_in[20];
    const float* w2  = (const float*)d_in[21];
    const float* b2  = (const float*)d_in[22];
    float* out = (float*)d_out;

    k_cvtW<<<1472, 256>>>(Wq, Wk_, Wv, aiw, aow, cw, w2);
    k_cvtX<<<SS*BB*CC, 256>>>(x);
    k_imp1<<<32, 256>>>(iw1, ib1);
    k_imp2<<<1, 32>>>(iw2, ib2);
    k_projT<<<dim3(32,2,36), 256>>>(bq, bnq, bk_, bnk, bv, bnv);
    k_attninT<<<dim3(32,2,36), 256>>>(aib);
    k_attn<<<dim3(64,8), 256>>>();
    k_outT<<<dim3(32,2,4), 256>>>(aob);
    k_convT<<<dim3(32,2,4), 256>>>(cb1, cbn);
    k_finalT<<<dim3(32,2,4), 256>>>(b2, x, out);
}

// round 9
// speedup vs baseline: 3.8719x; 1.1500x over previous
#include <cuda_runtime.h>
#include <cuda_bf16.h>
#include <cstdint>
#include <math.h>

#define SS 3
#define BB 4
#define CC 256
#define HW 4096
#define EPSf 1e-5f

// ---------------- scratch ----------------------------------------------------
__device__ float g_pooled[BB*SS*CC];
__device__ float g_h[BB*CC];
__device__ float g_wmix[BB*SS];
__device__ __align__(256) __nv_bfloat16 g_x_bf[SS*BB*CC*HW];
__device__ __align__(256) __nv_bfloat16 g_q [SS*BB*CC*HW];
__device__ __align__(256) __nv_bfloat16 g_k [SS*BB*CC*HW];
__device__ __align__(256) __nv_bfloat16 g_v [SS*BB*CC*HW];
__device__ __align__(256) __nv_bfloat16 g_qt[SS*BB*CC*HW];
__device__ __align__(256) __nv_bfloat16 g_kt[SS*BB*CC*HW];
__device__ __align__(256) __nv_bfloat16 g_vt[SS*BB*CC*HW];
__device__ __align__(256) __nv_bfloat16 g_o [SS*BB*CC*HW];
__device__ __align__(256) __nv_bfloat16 g_integr[BB*CC*HW];
__device__ __align__(256) __nv_bfloat16 g_y2[BB*CC*HW];
// bf16 weights
__device__ __align__(256) __nv_bfloat16 g_wq_bf [SS*CC*CC];
__device__ __align__(256) __nv_bfloat16 g_wk_bf [SS*CC*CC];
__device__ __align__(256) __nv_bfloat16 g_wv_bf [SS*CC*CC];
__device__ __align__(256) __nv_bfloat16 g_aiw_bf[3*CC*CC];
__device__ __align__(256) __nv_bfloat16 g_aow_bf[CC*CC];
__device__ __align__(256) __nv_bfloat16 g_cw_bf [CC*CC*9];   // r-major K: [m][r*256+c]
__device__ __align__(256) __nv_bfloat16 g_w2_bf [CC*CC];

__device__ __forceinline__ float gelu_f(float x){
    return 0.5f * x * (1.0f + erff(x * 0.70710678118654752f));
}
__device__ __forceinline__ uint32_t pkbf(float lo, float hi){
    __nv_bfloat162 h = __float22bfloat162_rn(make_float2(lo, hi));
    return *(uint32_t*)&h;
}
__device__ __forceinline__ __nv_bfloat162 pk2(float lo, float hi){
    return __float22bfloat162_rn(make_float2(lo, hi));
}
__device__ __forceinline__ void mma16(float c[4], const uint32_t a[4], const uint32_t b[2]){
    asm volatile(
        "mma.sync.aligned.m16n8k16.row.col.f32.bf16.bf16.f32 "
        "{%0,%1,%2,%3}, {%4,%5,%6,%7}, {%8,%9}, {%0,%1,%2,%3};"
        : "+f"(c[0]), "+f"(c[1]), "+f"(c[2]), "+f"(c[3])
        : "r"(a[0]), "r"(a[1]), "r"(a[2]), "r"(a[3]), "r"(b[0]), "r"(b[1]));
}

#define CP16(dst, src) asm volatile("cp.async.cg.shared.global [%0], [%1], 16;" :: "r"(dst), "l"(src))
#define CP_COMMIT()    asm volatile("cp.async.commit_group;" ::: "memory")
#define CP_WAIT1()     asm volatile("cp.async.wait_group 1;" ::: "memory")
#define CP_WAIT0()     asm volatile("cp.async.wait_group 0;" ::: "memory")
#define LDSM_X4(r, addr) \
    asm volatile("ldmatrix.sync.aligned.m8n8.x4.shared.b16 {%0,%1,%2,%3}, [%4];" \
        : "=r"((r)[0]), "=r"((r)[1]), "=r"((r)[2]), "=r"((r)[3]) : "r"(addr))
#define LDSM_X4T(r, addr) \
    asm volatile("ldmatrix.sync.aligned.m8n8.x4.trans.shared.b16 {%0,%1,%2,%3}, [%4];" \
        : "=r"((r)[0]), "=r"((r)[1]), "=r"((r)[2]), "=r"((r)[3]) : "r"(addr))

// ---------------- GEMM core ---------------------------------------------------
// CTA tile 128(M) x 128(N), BK=32 bf16, 256 thr = 8 warps (2M x 4N), warp 64x32.

__device__ __forceinline__ void cpA(uint32_t As, const __nv_bfloat16* W, int lda, int tid){
    #pragma unroll
    for(int i = 0; i < 2; i++){
        int id = tid + i*256;
        int m = id >> 2, u = id & 3;
        const __nv_bfloat16* src = W + (size_t)m*lda + u*8;
        uint32_t unit8 = (uint32_t)((((m&1)<<2) | u) ^ ((m>>1)&7));
        CP16(As + ((m>>1)<<7) + (unit8<<4), src);
    }
}
__device__ __forceinline__ void cpB(uint32_t Bs, const __nv_bfloat16* X, size_t stride, int tid){
    #pragma unroll
    for(int i = 0; i < 2; i++){
        int id = tid + i*256;
        int k = id >> 4, u = id & 15;
        const __nv_bfloat16* src = X + (size_t)k*stride + u*8;
        CP16(Bs + (k<<8) + (((uint32_t)(u ^ (k&7)))<<4), src);
    }
}

__device__ __forceinline__ void chunk_mma(uint32_t As, uint32_t Bs, float acc[4][4][4],
                                          int warp_m, int warp_n, int lane){
    int ml = lane & 15, sel = lane >> 4;
    #pragma unroll
    for(int kb = 0; kb < 2; kb++){
        uint32_t a[4][4], bb[2][4];
        #pragma unroll
        for(int mt = 0; mt < 4; mt++){
            int m = warp_m*64 + mt*16 + ml;
            int unit = kb*2 + sel;
            uint32_t addr = As + ((m>>1)<<7) +
                ((uint32_t)(((((m&1)<<2) | unit) ^ ((m>>1)&7)))<<4);
            LDSM_X4(a[mt], addr);
        }
        #pragma unroll
        for(int np = 0; np < 2; np++){
            int kk = kb*16 + ml;
            int u = warp_n*4 + np*2 + sel;
            uint32_t addr = Bs + (kk<<8) + (((uint32_t)(u ^ (kk&7)))<<4);
            LDSM_X4T(bb[np], addr);
        }
        #pragma unroll
        for(int mt = 0; mt < 4; mt++)
            #pragma unroll
            for(int nt = 0; nt < 4; nt++)
                mma16(acc[mt][nt], a[mt], bb[nt>>1] + ((nt&1)<<1));
    }
}

#define GEMM_PRE() \
    __shared__ __align__(16) uint32_t smA[3][2048]; \
    __shared__ __align__(16) uint32_t smB[3][2048]; \
    uint32_t AsB = (uint32_t)__cvta_generic_to_shared(smA); \
    uint32_t BsB = (uint32_t)__cvta_generic_to_shared(smB); \
    float acc[4][4][4]; \
    _Pragma("unroll") \
    for(int i=0;i<4;i++) _Pragma("unroll") for(int j=0;j<4;j++) _Pragma("unroll") for(int r=0;r<4;r++) acc[i][j][r]=0.f; \
    int tid = threadIdx.x; \
    int wid = tid >> 5, lane = tid & 31; \
    int warp_m = wid >> 2, warp_n = wid & 3; \
    int g = lane >> 2, tg = lane & 3; (void)g; (void)tg;

#define GEMM_LOOP(NK, APTR, BPTR) \
    cpA(AsB,        APTR(0), lda, tid); cpB(BsB,        BPTR(0), strideB, tid); CP_COMMIT(); \
    cpA(AsB + 8192, APTR(1), lda, tid); cpB(BsB + 8192, BPTR(1), strideB, tid); CP_COMMIT(); \
    for(int it = 0; it < (NK); it++){ \
        if(it + 1 < (NK)) { CP_WAIT1(); } else { CP_WAIT0(); } \
        __syncthreads(); \
        if(it + 2 < (NK)){ \
            int st = (it+2)%3; \
            cpA(AsB + st*8192, APTR(it+2), lda, tid); \
            cpB(BsB + st*8192, BPTR(it+2), strideB, tid); \
            CP_COMMIT(); \
        } \
        int cb = it % 3; \
        chunk_mma(AsB + cb*8192, BsB + cb*8192, acc, warp_m, warp_n, lane); \
    }

// ---------------- prep: weight conversion (conv K permuted to r-major) --------
__global__ void k_cvtW(const float* Wq, const float* Wk_, const float* Wv,
                       const float* aiw, const float* aow, const float* cw, const float* w2){
    int i = (blockIdx.x*256 + threadIdx.x) * 4;
    const float* src; __nv_bfloat16* dst; int off;
    if(i < 196608){ src=Wq;  dst=g_wq_bf;  off=i; }
    else if(i <  393216){ src=Wk_; dst=g_wk_bf;  off=i-196608; }
    else if(i <  589824){ src=Wv;  dst=g_wv_bf;  off=i-393216; }
    else if(i <  786432){ src=aiw; dst=g_aiw_bf; off=i-589824; }
    else if(i <  851968){ src=aow; dst=g_aow_bf; off=i-786432; }
    else if(i < 1441792){
        // conv weights: permute K from c*9+r to r*256+c
        int o4 = i - 851968;
        float4 v = *(const float4*)(cw + o4);
        float vv[4] = {v.x, v.y, v.z, v.w};
        #pragma unroll
        for(int j = 0; j < 4; j++){
            int o = o4 + j;
            int m = o / 2304;
            int rem = o - m*2304;
            int c = rem / 9;
            int r = rem - c*9;
            g_cw_bf[m*2304 + r*256 + c] = __float2bfloat16(vv[j]);
        }
        return;
    }
    else if(i < 1507328){ src=w2;  dst=g_w2_bf;  off=i-1441792; }
    else return;
    float4 v = *(const float4*)(src + off);
    uint2 o; o.x = pkbf(v.x, v.y); o.y = pkbf(v.z, v.w);
    *(uint2*)(dst + off) = o;
}

// ---------------- fused: x -> bf16 + channel mean pool -------------------------
__global__ void k_cvtX(const float* __restrict__ x){
    int id = blockIdx.x;
    int c = id & 255;
    int b = (id >> 8) & 3;
    int s = id >> 10;
    size_t base = (size_t)id * HW;
    const float4* src = (const float4*)(x + base);
    int t = threadIdx.x;
    float sum = 0.f;
    #pragma unroll
    for(int i = 0; i < 4; i++){
        int idx = t*4 + i*1024;
        float4 v = src[idx >> 2];
        sum += v.x + v.y + v.z + v.w;
        uint2 o; o.x = pkbf(v.x, v.y); o.y = pkbf(v.z, v.w);
        *(uint2*)(g_x_bf + base + idx) = o;
    }
    __shared__ float red[8];
    #pragma unroll
    for(int o = 16; o > 0; o >>= 1) sum += __shfl_down_sync(0xffffffffu, sum, o);
    if((t & 31) == 0) red[t >> 5] = sum;
    __syncthreads();
    if(t == 0){
        float tt = 0.f;
        #pragma unroll
        for(int i = 0; i < 8; i++) tt += red[i];
        g_pooled[(b*SS + s)*CC + c] = tt * (1.0f / HW);
    }
}

// ---------------- importance MLP ------------------------------------------------
__global__ void k_imp1(const float* __restrict__ iw1, const float* __restrict__ ib1){
    int warp = (blockIdx.x * 256 + threadIdx.x) >> 5;
    int lane = threadIdx.x & 31;
    const float* row = iw1 + (size_t)warp * (SS*CC);
    float a0=0.f, a1=0.f, a2=0.f, a3=0.f;
    for(int i = lane; i < SS*CC; i += 32){
        float w = row[i];
        a0 += w * g_pooled[0*(SS*CC)+i];
        a1 += w * g_pooled[1*(SS*CC)+i];
        a2 += w * g_pooled[2*(SS*CC)+i];
        a3 += w * g_pooled[3*(SS*CC)+i];
    }
    #pragma unroll
    for(int o = 16; o > 0; o >>= 1){
        a0 += __shfl_down_sync(0xffffffffu, a0, o);
        a1 += __shfl_down_sync(0xffffffffu, a1, o);
        a2 += __shfl_down_sync(0xffffffffu, a2, o);
        a3 += __shfl_down_sync(0xffffffffu, a3, o);
    }
    if(lane == 0){
        float bi = ib1[warp];
        g_h[0*CC+warp] = gelu_f(a0 + bi);
        g_h[1*CC+warp] = gelu_f(a1 + bi);
        g_h[2*CC+warp] = gelu_f(a2 + bi);
        g_h[3*CC+warp] = gelu_f(a3 + bi);
    }
}
// logits + softmax: 12 warps, one per (b,s)
__global__ void k_imp2(const float* __restrict__ iw2, const float* __restrict__ ib2){
    __shared__ float lg[12];
    int w = threadIdx.x >> 5, lane = threadIdx.x & 31;
    int b = w / SS, s = w - b*SS;
    float acc = 0.f;
    for(int c = lane; c < CC; c += 32) acc += g_h[b*CC+c] * iw2[s*CC + c];
    #pragma unroll
    for(int o = 16; o > 0; o >>= 1) acc += __shfl_down_sync(0xffffffffu, acc, o);
    if(lane == 0) lg[w] = acc + ib2[s];
    __syncthreads();
    if(threadIdx.x < BB){
        int bb = threadIdx.x;
        float l0 = lg[bb*3+0], l1 = lg[bb*3+1], l2 = lg[bb*3+2];
        float m  = fmaxf(l0, fmaxf(l1, l2));
        float e0 = expf(l0-m), e1 = expf(l1-m), e2 = expf(l2-m);
        float inv = 1.0f / (e0 + e1 + e2);
        g_wmix[bb*SS+0] = e0*inv; g_wmix[bb*SS+1] = e1*inv; g_wmix[bb*SS+2] = e2*inv;
    }
}

// ---------------- stage 3: q/k/v projection -----------------------------------
__global__ __launch_bounds__(256,2) void k_projT(
    const float* __restrict__ bq, const float* __restrict__ bnq,
    const float* __restrict__ bk_, const float* __restrict__ bnk,
    const float* __restrict__ bv, const float* __restrict__ bnv)
{
    int z = blockIdx.z;
    int which = z / 12;
    int s = (z % 12) >> 2;
    int b = z & 3;
    const __nv_bfloat16* W; const float *bias, *bn; __nv_bfloat16* out;
    if(which == 0){ W = g_wq_bf; bias = bq;  bn = bnq; out = g_q; }
    else if(which == 1){ W = g_wk_bf; bias = bk_; bn = bnk; out = g_k; }
    else { W = g_wv_bf; bias = bv; bn = bnv; out = g_v; }
    W += s * CC * CC;
    const __nv_bfloat16* X = g_x_bf + (size_t)(s*BB+b)*CC*HW;
    __nv_bfloat16*       O = out    + (size_t)(s*BB+b)*CC*HW;
    int m0 = blockIdx.y * 128;
    int n0 = blockIdx.x * 128;
    int lda = CC; size_t strideB = HW;

    GEMM_PRE();
    #define APTR(it) (W + (size_t)m0*CC + (it)*32)
    #define BPTR(it) (X + (size_t)(it)*32*HW + n0)
    GEMM_LOOP(8, APTR, BPTR)
    #undef APTR
    #undef BPTR
    #pragma unroll
    for(int mi = 0; mi < 4; mi++){
        int r0 = m0 + warp_m*64 + mi*16 + g;
        int r1 = r0 + 8;
        float sc0 = bn[(s*4+0)*CC+r0] * rsqrtf(bn[(s*4+3)*CC+r0] + EPSf);
        float sc1 = bn[(s*4+0)*CC+r1] * rsqrtf(bn[(s*4+3)*CC+r1] + EPSf);
        float be0 = bn[(s*4+1)*CC+r0], be1 = bn[(s*4+1)*CC+r1];
        float mu0 = bn[(s*4+2)*CC+r0], mu1 = bn[(s*4+2)*CC+r1];
        float bi0 = bias[s*CC+r0], bi1 = bias[s*CC+r1];
        #pragma unroll
        for(int ni = 0; ni < 4; ni++){
            int nc = n0 + warp_n*32 + ni*8 + tg*2;
            *(__nv_bfloat162*)&O[(size_t)r0*HW + nc] =
                pk2(gelu_f((acc[mi][ni][0] + bi0 - mu0)*sc0 + be0),
                    gelu_f((acc[mi][ni][1] + bi0 - mu0)*sc0 + be0));
            *(__nv_bfloat162*)&O[(size_t)r1*HW + nc] =
                pk2(gelu_f((acc[mi][ni][2] + bi1 - mu1)*sc1 + be1),
                    gelu_f((acc[mi][ni][3] + bi1 - mu1)*sc1 + be1));
        }
    }
}

// ---------------- stage 4: attn_in projection ---------------------------------
__global__ __launch_bounds__(256,2) void k_attninT(const float* __restrict__ aib)
{
    int z = blockIdx.z;
    int which = z / 12;
    int s = (z % 12) >> 2;
    int b = z & 3;
    const __nv_bfloat16* W = g_aiw_bf + which * CC * CC;
    const float* bias = aib + which * CC;
    const __nv_bfloat16* Xg; __nv_bfloat16* Og;
    if(which == 0){ Xg = g_q; Og = g_qt; }
    else if(which == 1){ Xg = g_k; Og = g_kt; }
    else { Xg = g_v; Og = g_vt; }
    const __nv_bfloat16* X = Xg + (size_t)(s*BB+b)*CC*HW;
    __nv_bfloat16*       O = Og + (size_t)(s*BB+b)*CC*HW;
    int m0 = blockIdx.y * 128;
    int n0 = blockIdx.x * 128;
    int lda = CC; size_t strideB = HW;

    GEMM_PRE();
    #define APTR(it) (W + (size_t)m0*CC + (it)*32)
    #define BPTR(it) (X + (size_t)(it)*32*HW + n0)
    GEMM_LOOP(8, APTR, BPTR)
    #undef APTR
    #undef BPTR
    #pragma unroll
    for(int mi = 0; mi < 4; mi++){
        int r0 = m0 + warp_m*64 + mi*16 + g;
        int r1 = r0 + 8;
        float bi0 = bias[r0], bi1 = bias[r1];
        #pragma unroll
        for(int ni = 0; ni < 4; ni++){
            int nc = n0 + warp_n*32 + ni*8 + tg*2;
            *(__nv_bfloat162*)&O[(size_t)r0*HW + nc] =
                pk2(acc[mi][ni][0] + bi0, acc[mi][ni][1] + bi0);
            *(__nv_bfloat162*)&O[(size_t)r1*HW + nc] =
                pk2(acc[mi][ni][2] + bi1, acc[mi][ni][3] + bi1);
        }
    }
}

// ---------------- stage 5: tiny attention over S=3 (bf16x2, + wmix fold) ------
__global__ void k_attn(){
    int idx = blockIdx.x * blockDim.x + threadIdx.x;   // 0..8191, 2 px each
    int head = blockIdx.y;
    int b = idx >> 11;
    int p = (idx << 1) & 4095;
    int off0 = ((0*BB+b)*CC)*HW + p;
    int off1 = ((1*BB+b)*CC)*HW + p;
    int off2 = ((2*BB+b)*CC)*HW + p;
    int cbase = head * 32;

    float2 sc[3][3];
    #pragma unroll
    for(int i=0;i<3;i++){
        #pragma unroll
        for(int j=0;j<3;j++){ sc[i][j].x = 0.f; sc[i][j].y = 0.f; }
    }

    #pragma unroll 4
    for(int d = 0; d < 32; d++){
        int co = (cbase + d) * HW;
        float2 q0 = __bfloat1622float2(*(const __nv_bfloat162*)&g_qt[off0+co]);
        float2 q1 = __bfloat1622float2(*(const __nv_bfloat162*)&g_qt[off1+co]);
        float2 q2 = __bfloat1622float2(*(const __nv_bfloat162*)&g_qt[off2+co]);
        float2 k0 = __bfloat1622float2(*(const __nv_bfloat162*)&g_kt[off0+co]);
        float2 k1 = __bfloat1622float2(*(const __nv_bfloat162*)&g_kt[off1+co]);
        float2 k2 = __bfloat1622float2(*(const __nv_bfloat162*)&g_kt[off2+co]);
        sc[0][0].x += q0.x*k0.x; sc[0][0].y += q0.y*k0.y;
        sc[0][1].x += q0.x*k1.x; sc[0][1].y += q0.y*k1.y;
        sc[0][2].x += q0.x*k2.x; sc[0][2].y += q0.y*k2.y;
        sc[1][0].x += q1.x*k0.x; sc[1][0].y += q1.y*k0.y;
        sc[1][1].x += q1.x*k1.x; sc[1][1].y += q1.y*k1.y;
        sc[1][2].x += q1.x*k2.x; sc[1][2].y += q1.y*k2.y;
        sc[2][0].x += q2.x*k0.x; sc[2][0].y += q2.y*k0.y;
        sc[2][1].x += q2.x*k1.x; sc[2][1].y += q2.y*k1.y;
        sc[2][2].x += q2.x*k2.x; sc[2][2].y += q2.y*k2.y;
    }
    const float scale = 0.17677669529663688f;
    float2 at[3][3];
    #pragma unroll
    for(int s_ = 0; s_ < 3; s_++){
        // component x
        {
            float a0 = sc[s_][0].x*scale, a1 = sc[s_][1].x*scale, a2 = sc[s_][2].x*scale;
            float m = fmaxf(a0, fmaxf(a1, a2));
            float e0 = expf(a0-m), e1 = expf(a1-m), e2 = expf(a2-m);
            float inv = 1.0f / (e0+e1+e2);
            at[s_][0].x = e0*inv; at[s_][1].x = e1*inv; at[s_][2].x = e2*inv;
        }
        // component y
        {
            float a0 = sc[s_][0].y*scale, a1 = sc[s_][1].y*scale, a2 = sc[s_][2].y*scale;
            float m = fmaxf(a0, fmaxf(a1, a2));
            float e0 = expf(a0-m), e1 = expf(a1-m), e2 = expf(a2-m);
            float inv = 1.0f / (e0+e1+e2);
            at[s_][0].y = e0*inv; at[s_][1].y = e1*inv; at[s_][2].y = e2*inv;
        }
    }
    float w0 = g_wmix[b*3+0], w1 = g_wmix[b*3+1], w2 = g_wmix[b*3+2];
    #pragma unroll 4
    for(int d = 0; d < 32; d++){
        int co = (cbase + d) * HW;
        float2 v0 = __bfloat1622float2(*(const __nv_bfloat162*)&g_vt[off0+co]);
        float2 v1 = __bfloat1622float2(*(const __nv_bfloat162*)&g_vt[off1+co]);
        float2 v2 = __bfloat1622float2(*(const __nv_bfloat162*)&g_vt[off2+co]);
        float ox0 = w0*(at[0][0].x*v0.x + at[0][1].x*v1.x + at[0][2].x*v2.x);
        float oy0 = w0*(at[0][0].y*v0.y + at[0][1].y*v1.y + at[0][2].y*v2.y);
        float ox1 = w1*(at[1][0].x*v0.x + at[1][1].x*v1.x + at[1][2].x*v2.x);
        float oy1 = w1*(at[1][0].y*v0.y + at[1][1].y*v1.y + at[1][2].y*v2.y);
        float ox2 = w2*(at[2][0].x*v0.x + at[2][1].x*v1.x + at[2][2].x*v2.x);
        float oy2 = w2*(at[2][0].y*v0.y + at[2][1].y*v1.y + at[2][2].y*v2.y);
        *(__nv_bfloat162*)&g_o[off0+co] = pk2(ox0, oy0);
        *(__nv_bfloat162*)&g_o[off1+co] = pk2(ox1, oy1);
        *(__nv_bfloat162*)&g_o[off2+co] = pk2(ox2, oy2);
    }
}

// ---------------- stage 6: attn_out GEMM (K=768, pre-scaled B) -----------------
__global__ __launch_bounds__(256,2) void k_outT(const float* __restrict__ bo)
{
    int b = blockIdx.z;
    int m0 = blockIdx.y * 128;
    int n0 = blockIdx.x * 128;
    int lda = CC; size_t strideB = HW;

    GEMM_PRE();
    #define APTR(it) (g_aow_bf + (size_t)m0*CC + (((it)*32) & 255))
    #define BPTR(it) (g_o + (size_t)(((((it)*32) >> 8)*BB + b)*CC + (((it)*32) & 255))*HW + n0)
    GEMM_LOOP(24, APTR, BPTR)
    #undef APTR
    #undef BPTR
    #pragma unroll
    for(int mi = 0; mi < 4; mi++){
        int r0 = m0 + warp_m*64 + mi*16 + g;
        int r1 = r0 + 8;
        float bi0 = bo[r0], bi1 = bo[r1];
        #pragma unroll
        for(int ni = 0; ni < 4; ni++){
            int nc = n0 + warp_n*32 + ni*8 + tg*2;
            *(__nv_bfloat162*)&g_integr[(size_t)(b*CC+r0)*HW + nc] =
                pk2(acc[mi][ni][0] + bi0, acc[mi][ni][1] + bi0);
            *(__nv_bfloat162*)&g_integr[(size_t)(b*CC+r1)*HW + nc] =
                pk2(acc[mi][ni][2] + bi1, acc[mi][ni][3] + bi1);
        }
    }
}

// ---------------- stage 7: 3x3 conv as GEMM (K=2304, r-major) ------------------
// chunk it: r = it>>3, c0 = (it&7)*32; uniform shift (dh,dw) per chunk.
__device__ __forceinline__ void gatherB_conv(uint4 rv[2], int b, int it, int n0, int tid){
    int r = it >> 3;
    int c0 = (it & 7) * 32;
    int kh = (r * 11) >> 5;           // r/3 for r in [0,9)
    int dw = (r - kh*3) - 1;
    int dh = kh - 1;
    #pragma unroll
    for(int i = 0; i < 2; i++){
        int id = tid + i*256;
        int krow = id >> 4, u = id & 15;
        const __nv_bfloat16* src = g_integr + (size_t)(b*CC + c0 + krow)*HW;
        int p0 = n0 + u*8;
        int h = p0 >> 6, w0 = p0 & 63;
        int hh = h + dh;
        uint4 out = make_uint4(0u,0u,0u,0u);
        if((unsigned)hh < 64u){
            const __nv_bfloat16* rp = src + hh*64 + w0;
            if(dw == 0){
                out = *(const uint4*)rp;
            } else if(dw > 0){
                uint4 v = *(const uint4*)rp;
                uint32_t nx = (w0 < 56) ? *(const uint32_t*)(rp + 8) : 0u;
                out.x = __byte_perm(v.x, v.y, 0x5432);
                out.y = __byte_perm(v.y, v.z, 0x5432);
                out.z = __byte_perm(v.z, v.w, 0x5432);
                out.w = __byte_perm(v.w, nx,  0x5432);
            } else {
                uint4 v = *(const uint4*)rp;
                uint32_t pv = (w0 > 0) ? *(const uint32_t*)(rp - 2) : 0u;
                out.x = __byte_perm(pv,  v.x, 0x5432);
                out.y = __byte_perm(v.x, v.y, 0x5432);
                out.z = __byte_perm(v.y, v.z, 0x5432);
                out.w = __byte_perm(v.z, v.w, 0x5432);
            }
        }
        rv[i] = out;
    }
}
__device__ __forceinline__ void stsB_conv(uint32_t* smBbuf, const uint4 rv[2], int tid){
    #pragma unroll
    for(int i = 0; i < 2; i++){
        int id = tid + i*256;
        int k = id >> 4, u = id & 15;
        int widx = k*64 + ((u ^ (k&7)) << 2);
        *(uint4*)&smBbuf[widx] = rv[i];
    }
}

__global__ __launch_bounds__(256,2) void k_convT(const float* __restrict__ b1,
                                                 const float* __restrict__ opbn)
{
    int b = blockIdx.z;
    int m0 = blockIdx.y * 128;
    int n0 = blockIdx.x * 128;
    const int lda = CC*9;
    const int nk = (CC*9)/32;   // 72

    GEMM_PRE();
    cpA(AsB,        g_cw_bf + (size_t)m0*lda + 0,  lda, tid); CP_COMMIT();
    cpA(AsB + 8192, g_cw_bf + (size_t)m0*lda + 32, lda, tid); CP_COMMIT();
    {
        uint4 rv[2];
        gatherB_conv(rv, b, 0, n0, tid);
        stsB_conv(smB[0], rv, tid);
    }
    for(int it = 0; it < nk; it++){
        if(it + 1 < nk) { CP_WAIT1(); } else { CP_WAIT0(); }
        __syncthreads();
        if(it + 2 < nk){
            int st = (it+2)%3;
            cpA(AsB + st*8192, g_cw_bf + (size_t)m0*lda + (it+2)*32, lda, tid);
            CP_COMMIT();
        }
        uint4 rv[2];
        if(it + 1 < nk) gatherB_conv(rv, b, it+1, n0, tid);
        int cb = it % 3;
        chunk_mma(AsB + cb*8192, BsB + cb*8192, acc, warp_m, warp_n, lane);
        if(it + 1 < nk) stsB_conv(smB[(it+1)%3], rv, tid);
    }
    #pragma unroll
    for(int mi = 0; mi < 4; mi++){
        int r0 = m0 + warp_m*64 + mi*16 + g;
        int r1 = r0 + 8;
        float sc0 = opbn[0*CC+r0] * rsqrtf(opbn[3*CC+r0] + EPSf);
        float sc1 = opbn[0*CC+r1] * rsqrtf(opbn[3*CC+r1] + EPSf);
        float be0 = opbn[1*CC+r0], be1 = opbn[1*CC+r1];
        float mu0 = opbn[2*CC+r0], mu1 = opbn[2*CC+r1];
        float bi0 = b1[r0], bi1 = b1[r1];
        #pragma unroll
        for(int ni = 0; ni < 4; ni++){
            int nc = n0 + warp_n*32 + ni*8 + tg*2;
            *(__nv_bfloat162*)&g_y2[(size_t)(b*CC+r0)*HW + nc] =
                pk2(gelu_f((acc[mi][ni][0] + bi0 - mu0)*sc0 + be0),
                    gelu_f((acc[mi][ni][1] + bi0 - mu0)*sc0 + be0));
            *(__nv_bfloat162*)&g_y2[(size_t)(b*CC+r1)*HW + nc] =
                pk2(gelu_f((acc[mi][ni][2] + bi1 - mu1)*sc1 + be1),
                    gelu_f((acc[mi][ni][3] + bi1 - mu1)*sc1 + be1));
        }
    }
}

// ---------------- stage 8: final 1x1 + residual --------------------------------
__global__ __launch_bounds__(256,2) void k_finalT(const float* __restrict__ b2,
                                                  const float* __restrict__ x,
                                                  float* __restrict__ out)
{
    int b = blockIdx.z;
    int m0 = blockIdx.y * 128;
    int n0 = blockIdx.x * 128;
    int lda = CC; size_t strideB = HW;

    GEMM_PRE();
    #define APTR(it) (g_w2_bf + (size_t)m0*CC + (it)*32)
    #define BPTR(it) (g_y2 + (size_t)(b*CC + (it)*32)*HW + n0)
    GEMM_LOOP(8, APTR, BPTR)
    #undef APTR
    #undef BPTR
    #pragma unroll
    for(int mi = 0; mi < 4; mi++){
        int r0 = m0 + warp_m*64 + mi*16 + g;
        int r1 = r0 + 8;
        float bi0 = b2[r0], bi1 = b2[r1];
        const float* res0 = x + (size_t)((1*BB+b)*CC + r0)*HW;
        const float* res1 = x + (size_t)((1*BB+b)*CC + r1)*HW;
        #pragma unroll
        for(int ni = 0; ni < 4; ni++){
            int nc = n0 + warp_n*32 + ni*8 + tg*2;
            float2 a0 = *(const float2*)&res0[nc];
            float2 a1 = *(const float2*)&res1[nc];
            float2 o0, o1;
            o0.x = acc[mi][ni][0] + bi0 + a0.x; o0.y = acc[mi][ni][1] + bi0 + a0.y;
            o1.x = acc[mi][ni][2] + bi1 + a1.x; o1.y = acc[mi][ni][3] + bi1 + a1.y;
            *(float2*)&out[(size_t)(b*CC+r0)*HW + nc] = o0;
            *(float2*)&out[(size_t)(b*CC+r1)*HW + nc] = o1;
        }
    }
}

// ---------------- launcher ------------------------------------------------------
extern "C" void kernel_launch(void* const* d_in, const int* in_sizes, int n_in,
                              void* d_out, int out_size)
{
    (void)in_sizes; (void)n_in; (void)out_size;
    const float* x   = (const float*)d_in[0];
    const float* Wq  = (const float*)d_in[1];
    const float* bq  = (const float*)d_in[2];
    const float* bnq = (const float*)d_in[3];
    const float* Wk_ = (const float*)d_in[4];
    const float* bk_ = (const float*)d_in[5];
    const float* bnk = (const float*)d_in[6];
    const float* Wv  = (const float*)d_in[7];
    const float* bv  = (const float*)d_in[8];
    const float* bnv = (const float*)d_in[9];
    const float* iw1 = (const float*)d_in[10];
    const float* ib1 = (const float*)d_in[11];
    const float* iw2 = (const float*)d_in[12];
    const float* ib2 = (const float*)d_in[13];
    const float* aiw = (const float*)d_in[14];
    const float* aib = (const float*)d_in[15];
    const float* aow = (const float*)d_in[16];
    const float* aob = (const float*)d_in[17];
    const float* cw  = (const float*)d_in[18];
    const float* cb1 = (const float*)d_in[19];
    const float* cbn = (const float*)d_in[20];
    const float* w2  = (const float*)d_in[21];
    const float* b2  = (const float*)d_in[22];
    float* out = (float*)d_out;

    k_cvtW<<<1472, 256>>>(Wq, Wk_, Wv, aiw, aow, cw, w2);
    k_cvtX<<<SS*BB*CC, 256>>>(x);
    k_imp1<<<32, 256>>>(iw1, ib1);
    k_imp2<<<1, 384>>>(iw2, ib2);
    k_projT<<<dim3(32,2,36), 256>>>(bq, bnq, bk_, bnk, bv, bnv);
    k_attninT<<<dim3(32,2,36), 256>>>(aib);
    k_attn<<<dim3(32,8), 256>>>();
    k_outT<<<dim3(32,2,4), 256>>>(aob);
    k_convT<<<dim3(32,2,4), 256>>>(cb1, cbn);
    k_finalT<<<dim3(32,2,4), 256>>>(b2, x, out);
}